// round 9
// baseline (speedup 1.0000x reference)
#include <cuda_runtime.h>
#include <cuda_bf16.h>
#include <cstdint>
#include <math.h>

#define N_SENTC 256
#define BATCH   512
#define SEQ     128
#define DIM     1024
#define LBL     10331
#define LATD    101
#define LATP    128          // padded K for latent GEMM
#define DIM2    2048
#define NEGV    (-10000.0f)

// ---------------- scratch -----------------------------------------------------
__device__ float g_C1[(size_t)N_SENTC * SEQ * DIM];
__device__ float g_menScore[N_SENTC * SEQ];
__device__ float g_ctxScore[BATCH * SEQ];
__device__ float g_final[BATCH * DIM2];
__device__ float g_m2[BATCH * DIM];

// bf16 hi/lo operand scratch
__device__ __nv_bfloat16 g_eH[(size_t)N_SENTC * SEQ * DIM];
__device__ __nv_bfloat16 g_eL[(size_t)N_SENTC * SEQ * DIM];
__device__ __nv_bfloat16 g_WmH[DIM * DIM],  g_WmL[DIM * DIM];
__device__ __nv_bfloat16 g_WcH[DIM * DIM],  g_WcL[DIM * DIM];
__device__ __nv_bfloat16 g_WcmH[DIM * DIM], g_WcmL[DIM * DIM];
__device__ __nv_bfloat16 g_WoH[(size_t)LBL * DIM2], g_WoL[(size_t)LBL * DIM2];
__device__ __nv_bfloat16 g_Wl2lH[(size_t)LBL * LATP], g_Wl2lL[(size_t)LBL * LATP];
__device__ __nv_bfloat16 g_fH[BATCH * DIM2], g_fL[BATCH * DIM2];
__device__ __nv_bfloat16 g_latH[BATCH * LATP], g_latL[BATCH * LATP];

// ---------------- helpers -----------------------------------------------------
__device__ __forceinline__ uint32_t smem_to_u32(const void* p) {
    uint32_t a;
    asm("{ .reg .u64 t; cvta.to.shared.u64 t, %1; cvt.u32.u64 %0, t; }" : "=r"(a) : "l"(p));
    return a;
}
__device__ __forceinline__ float ftanh(float x) {
    float e = __expf(2.0f * x);
    return 1.0f - __fdividef(2.0f, e + 1.0f);
}
__device__ __forceinline__ void split1(float x, __nv_bfloat16& h, __nv_bfloat16& l) {
    h = __float2bfloat16(x);
    l = __float2bfloat16(x - __bfloat162float(h));
}
__device__ __forceinline__ void split4(float4 v, uint2& hi, uint2& lo) {
    __nv_bfloat16 h[4], l[4];
    split1(v.x, h[0], l[0]); split1(v.y, h[1], l[1]);
    split1(v.z, h[2], l[2]); split1(v.w, h[3], l[3]);
    hi.x = (uint32_t)__bfloat16_as_ushort(h[0]) | ((uint32_t)__bfloat16_as_ushort(h[1]) << 16);
    hi.y = (uint32_t)__bfloat16_as_ushort(h[2]) | ((uint32_t)__bfloat16_as_ushort(h[3]) << 16);
    lo.x = (uint32_t)__bfloat16_as_ushort(l[0]) | ((uint32_t)__bfloat16_as_ushort(l[1]) << 16);
    lo.y = (uint32_t)__bfloat16_as_ushort(l[2]) | ((uint32_t)__bfloat16_as_ushort(l[3]) << 16);
}

__global__ void zero_kernel(float* p, int n) {
    int i = blockIdx.x * blockDim.x + threadIdx.x;
    if (i < n) p[i] = 0.0f;
}

__global__ void cvt_hilo(const float* __restrict__ src, __nv_bfloat16* __restrict__ h,
                         __nv_bfloat16* __restrict__ l, int n4) {
    int i = blockIdx.x * blockDim.x + threadIdx.x;
    if (i < n4) {
        float4 v = reinterpret_cast<const float4*>(src)[i];
        uint2 hi, lo; split4(v, hi, lo);
        reinterpret_cast<uint2*>(h)[i] = hi;
        reinterpret_cast<uint2*>(l)[i] = lo;
    }
}

// W_l2l [LBL,101] fp32 -> [LBL,128] bf16 hi/lo (zero-padded)
__global__ void cvt_l2l(const float* __restrict__ src,
                        __nv_bfloat16* __restrict__ h, __nv_bfloat16* __restrict__ l) {
    int i = blockIdx.x * blockDim.x + threadIdx.x;
    if (i < LBL * LATP) {
        int r = i >> 7, c = i & 127;
        float v = (c < LATD) ? src[r * LATD + c] : 0.0f;
        __nv_bfloat16 hh, ll; split1(v, hh, ll);
        h[i] = hh; l[i] = ll;
    }
}

// ---------------- warp-mma + cp.async primitives ------------------------------
__device__ __forceinline__ void ldsm4(uint32_t* r, uint32_t addr) {
    asm volatile("ldmatrix.sync.aligned.m8n8.x4.shared.b16 {%0,%1,%2,%3}, [%4];"
                 : "=r"(r[0]), "=r"(r[1]), "=r"(r[2]), "=r"(r[3]) : "r"(addr));
}
__device__ __forceinline__ void mma16816(float (&c)[4], const uint32_t* a, const uint32_t* b) {
    asm volatile("mma.sync.aligned.m16n8k16.row.col.f32.bf16.bf16.f32 "
                 "{%0,%1,%2,%3}, {%4,%5,%6,%7}, {%8,%9}, {%0,%1,%2,%3};"
                 : "+f"(c[0]), "+f"(c[1]), "+f"(c[2]), "+f"(c[3])
                 : "r"(a[0]), "r"(a[1]), "r"(a[2]), "r"(a[3]), "r"(b[0]), "r"(b[1]));
}
__device__ __forceinline__ void cp16(uint32_t saddr, const void* gaddr, int src_size) {
    asm volatile("cp.async.cg.shared.global [%0], [%1], 16, %2;"
                 :: "r"(saddr), "l"(gaddr), "r"(src_size) : "memory");
}
#define CP_COMMIT() asm volatile("cp.async.commit_group;" ::: "memory")
#define CP_WAIT1()  asm volatile("cp.async.wait_group 1;" ::: "memory")
#define CP_WAIT0()  asm volatile("cp.async.wait_group 0;" ::: "memory")

// stage: A 128x64 bf16 hi/lo + B 256x64 bf16 hi/lo (128B rows, XOR-8 swizzle)
#define AH_OFF 0
#define AL_OFF 16384
#define BH_OFF 32768
#define BL_OFF 65536
#define STAGE_BYTES 98304
#define SMEM_GEMM (2 * STAGE_BYTES)

// ---------------- shared GEMM core: acc += A*B^T over K (bf16 hi/lo, 3-pass) --
// CTA tile 128(M) x 256(N), warp tile 64x64, BK=64, 256 thr, 2-stage cp.async.
// Requires: M mult of 128 (A rows unguarded), K mult of 64, rows 16B-aligned.
__device__ __forceinline__ void gemm_core(
    const __nv_bfloat16* __restrict__ AH_, const __nv_bfloat16* __restrict__ AL_, int lda,
    const __nv_bfloat16* __restrict__ BH_, const __nv_bfloat16* __restrict__ BL_, int ldb,
    int N, int K, int m0, int n0, char* smem, float (&acc)[4][8][4])
{
    const uint32_t sb = smem_to_u32(smem);
    const int tid  = threadIdx.x;
    const int lane = tid & 31;
    const int wid  = tid >> 5;
    const int wm0  = (wid >> 2) * 64;
    const int wn0  = (wid & 3) * 64;
    const int nk   = K >> 6;

#pragma unroll
    for (int i = 0; i < 4; i++)
#pragma unroll
        for (int j = 0; j < 8; j++)
#pragma unroll
            for (int q = 0; q < 4; q++) acc[i][j][q] = 0.0f;

    const int aRow = lane & 15, aSel = lane >> 4;
    const int bRow = (lane & 7) + ((lane >> 4) << 3);
    const int bSel = (lane >> 3) & 1;
    const int crow = tid >> 3;          // 0..31
    const int cch  = tid & 7;           // 16B chunk

    auto issue = [&](int c) {
        if (c >= nk) return;
        const int kb = c * 64;
        uint32_t stb = sb + (c & 1) * STAGE_BYTES;
#pragma unroll
        for (int q = 0; q < 4; q++) {
            int row = crow + q * 32;
            uint32_t so = (uint32_t)(row * 128 + (((cch ^ (row & 7)) & 7) << 4));
            size_t ga = (size_t)(m0 + row) * lda + kb + cch * 8;
            cp16(stb + AH_OFF + so, AH_ + ga, 16);
            cp16(stb + AL_OFF + so, AL_ + ga, 16);
        }
#pragma unroll
        for (int q = 0; q < 8; q++) {
            int row = crow + q * 32;
            uint32_t so = (uint32_t)(row * 128 + (((cch ^ (row & 7)) & 7) << 4));
            int br = n0 + row;
            int ok = (br < N) ? 16 : 0;
            size_t gb = (size_t)min(br, N - 1) * ldb + kb + cch * 8;
            cp16(stb + BH_OFF + so, BH_ + gb, ok);
            cp16(stb + BL_OFF + so, BL_ + gb, ok);
        }
    };

    issue(0); CP_COMMIT();
    issue(1); CP_COMMIT();

    for (int c = 0; c < nk; c++) {
        if (c + 1 < nk) { CP_WAIT1(); } else { CP_WAIT0(); }
        __syncthreads();
        uint32_t stb = sb + (c & 1) * STAGE_BYTES;
#pragma unroll
        for (int ks = 0; ks < 4; ks++) {
            const int kc = ks * 2;
            uint32_t aH[4][4], aL[4][4];
#pragma unroll
            for (int mf = 0; mf < 4; mf++) {
                int r = wm0 + mf * 16 + aRow;
                int ch = kc + aSel;
                uint32_t o = (uint32_t)(r * 128 + (((ch ^ (r & 7)) & 7) << 4));
                ldsm4(aH[mf], stb + AH_OFF + o);
                ldsm4(aL[mf], stb + AL_OFF + o);
            }
#pragma unroll
            for (int nh = 0; nh < 2; nh++) {
                uint32_t bH[2][4], bL[2][4];
#pragma unroll
                for (int p = 0; p < 2; p++) {
                    int r = wn0 + nh * 32 + p * 16 + bRow;
                    int ch = kc + bSel;
                    uint32_t o = (uint32_t)(r * 128 + (((ch ^ (r & 7)) & 7) << 4));
                    ldsm4(bH[p], stb + BH_OFF + o);
                    ldsm4(bL[p], stb + BL_OFF + o);
                }
#pragma unroll
                for (int mf = 0; mf < 4; mf++) {
#pragma unroll
                    for (int nf = 0; nf < 4; nf++) {
                        const int nn = nh * 4 + nf;
                        const uint32_t* bh = &bH[nf >> 1][(nf & 1) * 2];
                        const uint32_t* bl = &bL[nf >> 1][(nf & 1) * 2];
                        mma16816(acc[mf][nn], aH[mf], bh);
                        mma16816(acc[mf][nn], aL[mf], bh);
                        mma16816(acc[mf][nn], aH[mf], bl);
                    }
                }
            }
        }
        __syncthreads();
        issue(c + 2); CP_COMMIT();
    }
}

// ---------------- fused big kernel: mention scores + C1 -----------------------
// grid (8, 256): x<4 -> B=W_men_m, tanh*wo row-reduce; x>=4 -> B=W_ctx_c, store C1
__global__ __launch_bounds__(256, 1)
void gemm_big(const __nv_bfloat16* __restrict__ eH, const __nv_bfloat16* __restrict__ eL,
              const __nv_bfloat16* __restrict__ wmH, const __nv_bfloat16* __restrict__ wmL,
              const __nv_bfloat16* __restrict__ wcH, const __nv_bfloat16* __restrict__ wcL,
              const float* __restrict__ wo, float* __restrict__ rowAcc,
              float* __restrict__ C1)
{
    extern __shared__ char smem[];
    const bool isMen = blockIdx.x < 4;
    const int n0 = (blockIdx.x & 3) * 256;
    const int m0 = blockIdx.y * 128;
    const int lane = threadIdx.x & 31;
    const int wid  = threadIdx.x >> 5;
    const int wm0  = (wid >> 2) * 64;
    const int wn0  = (wid & 3) * 64;

    float acc[4][8][4];
    gemm_core(eH, eL, DIM, isMen ? wmH : wcH, isMen ? wmL : wcL, DIM,
              DIM, DIM, m0, n0, smem, acc);

    const int g = lane >> 2, t = lane & 3;
    if (isMen) {
#pragma unroll
        for (int mf = 0; mf < 4; mf++) {
            float s0 = 0.0f, s1 = 0.0f;
#pragma unroll
            for (int nf = 0; nf < 8; nf++) {
#pragma unroll
                for (int q = 0; q < 2; q++) {
                    int n = n0 + wn0 + nf * 8 + 2 * t + q;
                    float w = wo[n];
                    s0 += ftanh(acc[mf][nf][q])     * w;
                    s1 += ftanh(acc[mf][nf][2 + q]) * w;
                }
            }
            s0 += __shfl_xor_sync(0xffffffffu, s0, 1);
            s0 += __shfl_xor_sync(0xffffffffu, s0, 2);
            s1 += __shfl_xor_sync(0xffffffffu, s1, 1);
            s1 += __shfl_xor_sync(0xffffffffu, s1, 2);
            if (t == 0) {
                int m = m0 + wm0 + mf * 16 + g;
                atomicAdd(&rowAcc[m], s0);
                atomicAdd(&rowAcc[m + 8], s1);
            }
        }
    } else {
#pragma unroll
        for (int mf = 0; mf < 4; mf++) {
            int mA = m0 + wm0 + mf * 16 + g;
#pragma unroll
            for (int nf = 0; nf < 8; nf++) {
                int n = n0 + wn0 + nf * 8 + 2 * t;
                size_t iA = (size_t)mA * DIM + n;
                size_t iB = (size_t)(mA + 8) * DIM + n;
                C1[iA]     = acc[mf][nf][0];
                C1[iA + 1] = acc[mf][nf][1];
                C1[iB]     = acc[mf][nf][2];
                C1[iB + 1] = acc[mf][nf][3];
            }
        }
    }
}

// ---------------- generic GEMM kernel (STORE / OUT epilogues) -----------------
enum { MODE_STORE = 0, MODE_OUT = 2 };

template <int MODE>
__global__ __launch_bounds__(256, 1)
void gemm_bf(const __nv_bfloat16* __restrict__ AH_, const __nv_bfloat16* __restrict__ AL_, int lda,
             const __nv_bfloat16* __restrict__ BH_, const __nv_bfloat16* __restrict__ BL_, int ldb,
             float* __restrict__ C, int ldc, int N, int K,
             const float* __restrict__ aux, const float* __restrict__ scal)
{
    extern __shared__ char smem[];
    const int n0 = blockIdx.x * 256;
    const int m0 = blockIdx.y * 128;
    const int lane = threadIdx.x & 31;
    const int wid  = threadIdx.x >> 5;
    const int wm0  = (wid >> 2) * 64;
    const int wn0  = (wid & 3) * 64;

    float acc[4][8][4];
    gemm_core(AH_, AL_, lda, BH_, BL_, ldb, N, K, m0, n0, smem, acc);

    const int g = lane >> 2, t = lane & 3;
    const float ls = (MODE == MODE_OUT) ? *scal : 0.0f;
#pragma unroll
    for (int mf = 0; mf < 4; mf++) {
        int mA = m0 + wm0 + mf * 16 + g;
#pragma unroll
        for (int nf = 0; nf < 8; nf++) {
            int n = n0 + wn0 + nf * 8 + 2 * t;
#pragma unroll
            for (int q = 0; q < 2; q++) {
                int nn = n + q;
                if (nn < N) {
                    size_t iA = (size_t)mA * ldc + nn;
                    size_t iB = (size_t)(mA + 8) * ldc + nn;
                    float v0 = acc[mf][nf][q];
                    float v1 = acc[mf][nf][2 + q];
                    if (MODE == MODE_OUT) { v0 += ls * aux[iA]; v1 += ls * aux[iB]; }
                    C[iA] = v0;
                    C[iB] = v1;
                }
            }
        }
    }
}

// ---------------- masked softmax over S + weighted sum ------------------------
__global__ void attn_kernel(const float* __restrict__ elmo,
                            const int* __restrict__ gathers,
                            const float* __restrict__ scores,
                            const float* __restrict__ mask,
                            int gatherScores,
                            float* __restrict__ outBase,
                            __nv_bfloat16* __restrict__ outH,
                            __nv_bfloat16* __restrict__ outL)
{
    int b = blockIdx.x;
    int tid = threadIdx.x;
    __shared__ float attn_s[SEQ];
    __shared__ float red[8];
    int g = gathers[b];

    float sc = -1e30f;
    if (tid < SEQ) {
        float raw = gatherScores ? scores[g * SEQ + tid] : scores[b * SEQ + tid];
        sc = raw + (1.0f - mask[b * SEQ + tid]) * NEGV;
    }
    float v = sc;
#pragma unroll
    for (int off = 16; off > 0; off >>= 1)
        v = fmaxf(v, __shfl_xor_sync(0xffffffffu, v, off));
    if ((tid & 31) == 0) red[tid >> 5] = v;
    __syncthreads();
    float mx = fmaxf(fmaxf(red[0], red[1]), fmaxf(red[2], red[3]));
    __syncthreads();

    float e = (tid < SEQ) ? __expf(sc - mx) : 0.0f;
    v = e;
#pragma unroll
    for (int off = 16; off > 0; off >>= 1)
        v += __shfl_xor_sync(0xffffffffu, v, off);
    if ((tid & 31) == 0) red[tid >> 5] = v;
    __syncthreads();
    float sum = red[0] + red[1] + red[2] + red[3];
    if (tid < SEQ) attn_s[tid] = e / sum;
    __syncthreads();

    const float4* xr = reinterpret_cast<const float4*>(elmo + (size_t)g * SEQ * DIM);
    float4 accv = make_float4(0.f, 0.f, 0.f, 0.f);
#pragma unroll 4
    for (int s = 0; s < SEQ; s++) {
        float a = attn_s[s];
        float4 x = xr[(size_t)s * (DIM / 4) + tid];
        accv.x = fmaf(a, x.x, accv.x);
        accv.y = fmaf(a, x.y, accv.y);
        accv.z = fmaf(a, x.z, accv.z);
        accv.w = fmaf(a, x.w, accv.w);
    }
    size_t idx = (size_t)b * DIM2 + 4 * tid;
    *reinterpret_cast<float4*>(outBase + idx) = accv;
    uint2 hi, lo; split4(accv, hi, lo);
    *reinterpret_cast<uint2*>(outH + idx) = hi;
    *reinterpret_cast<uint2*>(outL + idx) = lo;
}

// ---------------- fused context score (warp-per-s) ----------------------------
__global__ void ctx_score_kernel(const int* __restrict__ gathers,
                                 const float* __restrict__ dist,
                                 const float* __restrict__ wd,
                                 const float* __restrict__ wo)
{
    int b = blockIdx.x;
    int tid = threadIdx.x;
    int w = tid >> 5, lid = tid & 31;
    __shared__ __align__(16) float s_m2[DIM];
    __shared__ __align__(16) float s_wd[DIM];
    __shared__ __align__(16) float s_wo[DIM];
    int g = gathers[b];
    for (int i = tid; i < DIM; i += 256) {
        s_m2[i] = g_m2[(size_t)b * DIM + i];
        s_wd[i] = wd[i];
        s_wo[i] = wo[i];
    }
    __syncthreads();

    const float4* c1 = reinterpret_cast<const float4*>(g_C1) + (size_t)g * SEQ * (DIM / 4);
    const float4* m2v = reinterpret_cast<const float4*>(s_m2);
    const float4* wdv = reinterpret_cast<const float4*>(s_wd);
    const float4* wov = reinterpret_cast<const float4*>(s_wo);

    for (int s = w; s < SEQ; s += 8) {
        float dv = dist[b * SEQ + s];
        float p = 0.0f;
#pragma unroll
        for (int j0 = 0; j0 < 8; j0++) {
            int j = lid + j0 * 32;
            float4 c = c1[(size_t)s * (DIM / 4) + j];
            float4 m = m2v[j], d = wdv[j], o = wov[j];
            p += o.x * ftanh(c.x + m.x + dv * d.x)
               + o.y * ftanh(c.y + m.y + dv * d.y)
               + o.z * ftanh(c.z + m.z + dv * d.z)
               + o.w * ftanh(c.w + m.w + dv * d.w);
        }
#pragma unroll
        for (int off = 16; off > 0; off >>= 1)
            p += __shfl_xor_sync(0xffffffffu, p, off);
        if (lid == 0) g_ctxScore[b * SEQ + s] = p;
    }
}

// ---------------- latent = final @ W_f2l^T -> bf16 hi/lo padded ---------------
__global__ void latent_kernel(const float* __restrict__ Wf2l)
{
    int b = blockIdx.x;
    int tid = threadIdx.x;   // 128 threads
    __shared__ __align__(16) float4 sf[DIM2 / 4];
    const float4* fr = reinterpret_cast<const float4*>(&g_final[(size_t)b * DIM2]);
    for (int i = tid; i < DIM2 / 4; i += 128) sf[i] = fr[i];
    __syncthreads();
    float acc = 0.0f;
    if (tid < LATD) {
        const float4* wr = reinterpret_cast<const float4*>(Wf2l + (size_t)tid * DIM2);
#pragma unroll 4
        for (int k = 0; k < DIM2 / 4; k++) {
            float4 wv = wr[k];
            float4 f = sf[k];
            acc += wv.x * f.x + wv.y * f.y + wv.z * f.z + wv.w * f.w;
        }
    }
    __nv_bfloat16 h, l; split1(tid < LATD ? acc : 0.0f, h, l);
    g_latH[b * LATP + tid] = h;
    g_latL[b * LATP + tid] = l;
}

// ---------------- launch ------------------------------------------------------
extern "C" void kernel_launch(void* const* d_in, const int* in_sizes, int n_in,
                              void* d_out, int out_size)
{
    const float* elmo     = (const float*)d_in[0];
    const float* men_mask = (const float*)d_in[1];
    const float* ctx_mask = (const float*)d_in[2];
    const float* dist     = (const float*)d_in[3];
    const int*   gathers  = (const int*)  d_in[4];
    const float* W_men_m  = (const float*)d_in[5];
    const float* W_men_o  = (const float*)d_in[6];
    const float* W_ctx_c  = (const float*)d_in[7];
    const float* W_ctx_m  = (const float*)d_in[8];
    const float* w_ctx_d  = (const float*)d_in[9];
    const float* W_ctx_o  = (const float*)d_in[10];
    const float* W_out    = (const float*)d_in[11];
    const float* W_f2l    = (const float*)d_in[12];
    const float* W_l2l    = (const float*)d_in[13];
    const float* lscal    = (const float*)d_in[14];

    float* out_main = (float*)d_out;
    float* out_lat  = out_main + (size_t)BATCH * LBL;

    float *pC1, *pMS, *pCS, *pFin, *pM2;
    cudaGetSymbolAddress((void**)&pC1,  g_C1);
    cudaGetSymbolAddress((void**)&pMS,  g_menScore);
    cudaGetSymbolAddress((void**)&pCS,  g_ctxScore);
    cudaGetSymbolAddress((void**)&pFin, g_final);
    cudaGetSymbolAddress((void**)&pM2,  g_m2);
    __nv_bfloat16 *pEH, *pEL, *pWmH, *pWmL, *pWcH, *pWcL, *pWcmH, *pWcmL;
    __nv_bfloat16 *pWoH, *pWoL, *pl2lH, *pl2lL, *pFH, *pFL, *pLaH, *pLaL;
    cudaGetSymbolAddress((void**)&pEH,   g_eH);
    cudaGetSymbolAddress((void**)&pEL,   g_eL);
    cudaGetSymbolAddress((void**)&pWmH,  g_WmH);
    cudaGetSymbolAddress((void**)&pWmL,  g_WmL);
    cudaGetSymbolAddress((void**)&pWcH,  g_WcH);
    cudaGetSymbolAddress((void**)&pWcL,  g_WcL);
    cudaGetSymbolAddress((void**)&pWcmH, g_WcmH);
    cudaGetSymbolAddress((void**)&pWcmL, g_WcmL);
    cudaGetSymbolAddress((void**)&pWoH,  g_WoH);
    cudaGetSymbolAddress((void**)&pWoL,  g_WoL);
    cudaGetSymbolAddress((void**)&pl2lH, g_Wl2lH);
    cudaGetSymbolAddress((void**)&pl2lL, g_Wl2lL);
    cudaGetSymbolAddress((void**)&pFH,   g_fH);
    cudaGetSymbolAddress((void**)&pFL,   g_fL);
    cudaGetSymbolAddress((void**)&pLaH,  g_latH);
    cudaGetSymbolAddress((void**)&pLaL,  g_latL);

    cudaFuncSetAttribute(gemm_big,            cudaFuncAttributeMaxDynamicSharedMemorySize, SMEM_GEMM);
    cudaFuncSetAttribute(gemm_bf<MODE_STORE>, cudaFuncAttributeMaxDynamicSharedMemorySize, SMEM_GEMM);
    cudaFuncSetAttribute(gemm_bf<MODE_OUT>,   cudaFuncAttributeMaxDynamicSharedMemorySize, SMEM_GEMM);

    // launches 0-4 (so that launch index 5 = gemm_big, for ncu -s 5 -c 1)
    zero_kernel<<<(N_SENTC * SEQ + 255) / 256, 256>>>(pMS, N_SENTC * SEQ);           // 0
    {
        int n4 = (N_SENTC * SEQ * DIM) / 4;
        cvt_hilo<<<(n4 + 255) / 256, 256>>>(elmo, pEH, pEL, n4);                     // 1
        n4 = (DIM * DIM) / 4;
        cvt_hilo<<<(n4 + 255) / 256, 256>>>(W_men_m, pWmH, pWmL, n4);                // 2
        cvt_hilo<<<(n4 + 255) / 256, 256>>>(W_ctx_c, pWcH, pWcL, n4);                // 3
        int n4o = (int)(((size_t)LBL * DIM2) / 4);
        cvt_hilo<<<(n4o + 255) / 256, 256>>>(W_out, pWoH, pWoL, n4o);                // 4
    }

    // 5. fused big GEMM: mention scores (x<4) + C1 (x>=4)
    gemm_big<<<dim3(8, 256), 256, SMEM_GEMM>>>(
        pEH, pEL, pWmH, pWmL, pWcH, pWcL, W_men_o, pMS, pC1);

    // remaining conversions (needed later)
    {
        int n4 = (DIM * DIM) / 4;
        cvt_hilo<<<(n4 + 255) / 256, 256>>>(W_ctx_m, pWcmH, pWcmL, n4);              // 6
        cvt_l2l<<<(LBL * LATP + 255) / 256, 256>>>(W_l2l, pl2lH, pl2lL);             // 7
    }

    // mention softmax + men_repr -> final cols [0,1024)
    attn_kernel<<<BATCH, 256>>>(elmo, gathers, pMS, men_mask, 1, pFin, pFH, pFL);

    // m2 = men_repr @ W_ctx_m^T
    gemm_bf<MODE_STORE><<<dim3(4, 4), 256, SMEM_GEMM>>>(
        pFH, pFL, DIM2, pWcmH, pWcmL, DIM, pM2, DIM, DIM, DIM, nullptr, nullptr);

    // fused context scores
    ctx_score_kernel<<<BATCH, 256>>>(gathers, dist, w_ctx_d, W_ctx_o);

    // context softmax + ctx_repr -> final cols [1024,2048)
    attn_kernel<<<BATCH, 256>>>(elmo, gathers, pCS, ctx_mask, 0,
                                pFin + DIM, pFH + DIM, pFL + DIM);

    // latent = final @ W_f2l^T -> bf16 hi/lo padded [512,128]
    latent_kernel<<<BATCH, 128>>>(W_f2l);

    // outputs_latent = latent @ W_l2l^T  (M=512, N=10331, K=128)
    gemm_bf<MODE_STORE><<<dim3(41, 4), 256, SMEM_GEMM>>>(
        pLaH, pLaL, LATP, pl2lH, pl2lL, LATP, out_lat, LBL, LBL, LATP, nullptr, nullptr);

    // outputs = final @ W_out^T + latent_scalar * outputs_latent
    gemm_bf<MODE_OUT><<<dim3(41, 4), 256, SMEM_GEMM>>>(
        pFH, pFL, DIM2, pWoH, pWoL, DIM2, out_main, LBL, LBL, DIM2, out_lat, lscal);
}

// round 10
// speedup vs baseline: 1.8931x; 1.8931x over previous
#include <cuda_runtime.h>
#include <cuda_fp16.h>
#include <cstdint>
#include <math.h>

#define N_SENTC 256
#define BATCH   512
#define SEQ     128
#define DIM     1024
#define LBL     10331
#define LATD    101
#define LATP    128
#define DIM2    2048
#define NEGV    (-10000.0f)

// ---------------- scratch -----------------------------------------------------
__device__ float g_C1[(size_t)N_SENTC * SEQ * DIM];
__device__ float g_menScore[N_SENTC * SEQ];
__device__ float g_ctxScore[BATCH * SEQ];
__device__ float g_final[BATCH * DIM2];
__device__ float g_m2[BATCH * DIM];

// fp16 operand scratch
__device__ __half g_eF[(size_t)N_SENTC * SEQ * DIM];
__device__ __half g_WmF[DIM * DIM];
__device__ __half g_WcF[DIM * DIM];
__device__ __half g_WcmF[DIM * DIM];
__device__ __half g_WoF[(size_t)LBL * DIM2];
__device__ __half g_Wl2lF[(size_t)LBL * LATP];
__device__ __half g_fF[BATCH * DIM2];
__device__ __half g_latF[BATCH * LATP];

// ---------------- helpers -----------------------------------------------------
__device__ __forceinline__ uint32_t smem_to_u32(const void* p) {
    uint32_t a;
    asm("{ .reg .u64 t; cvta.to.shared.u64 t, %1; cvt.u32.u64 %0, t; }" : "=r"(a) : "l"(p));
    return a;
}
__device__ __forceinline__ float ftanh(float x) {
    float e = __expf(2.0f * x);
    return 1.0f - __fdividef(2.0f, e + 1.0f);
}

__global__ void zero_kernel(float* p, int n) {
    int i = blockIdx.x * blockDim.x + threadIdx.x;
    if (i < n) p[i] = 0.0f;
}

// fp32 -> fp16 (n4 float4 groups)
__global__ void cvt_f16(const float* __restrict__ src, __half* __restrict__ dst, int n4) {
    int i = blockIdx.x * blockDim.x + threadIdx.x;
    if (i < n4) {
        float4 v = reinterpret_cast<const float4*>(src)[i];
        __half2 a = __floats2half2_rn(v.x, v.y);
        __half2 b = __floats2half2_rn(v.z, v.w);
        uint2 o;
        o.x = *reinterpret_cast<uint32_t*>(&a);
        o.y = *reinterpret_cast<uint32_t*>(&b);
        reinterpret_cast<uint2*>(dst)[i] = o;
    }
}

// W_l2l [LBL,101] fp32 -> [LBL,128] fp16 zero-padded
__global__ void cvt_l2l(const float* __restrict__ src, __half* __restrict__ dst) {
    int i = blockIdx.x * blockDim.x + threadIdx.x;
    if (i < LBL * LATP) {
        int r = i >> 7, c = i & 127;
        float v = (c < LATD) ? src[r * LATD + c] : 0.0f;
        dst[i] = __float2half_rn(v);
    }
}

// ---------------- warp-mma + cp.async primitives ------------------------------
__device__ __forceinline__ void ldsm4(uint32_t* r, uint32_t addr) {
    asm volatile("ldmatrix.sync.aligned.m8n8.x4.shared.b16 {%0,%1,%2,%3}, [%4];"
                 : "=r"(r[0]), "=r"(r[1]), "=r"(r[2]), "=r"(r[3]) : "r"(addr));
}
__device__ __forceinline__ void mma16816(float (&c)[4], const uint32_t* a, const uint32_t* b) {
    asm volatile("mma.sync.aligned.m16n8k16.row.col.f32.f16.f16.f32 "
                 "{%0,%1,%2,%3}, {%4,%5,%6,%7}, {%8,%9}, {%0,%1,%2,%3};"
                 : "+f"(c[0]), "+f"(c[1]), "+f"(c[2]), "+f"(c[3])
                 : "r"(a[0]), "r"(a[1]), "r"(a[2]), "r"(a[3]), "r"(b[0]), "r"(b[1]));
}
__device__ __forceinline__ void cp16(uint32_t saddr, const void* gaddr, int src_size) {
    asm volatile("cp.async.cg.shared.global [%0], [%1], 16, %2;"
                 :: "r"(saddr), "l"(gaddr), "r"(src_size) : "memory");
}
#define CP_COMMIT() asm volatile("cp.async.commit_group;" ::: "memory")
#define CP_WAIT2()  asm volatile("cp.async.wait_group 2;" ::: "memory")

// stage: A 128x64 fp16 (16KB) + B 256x64 fp16 (32KB); 128B rows, XOR-8 swizzle
#define A_OFF 0
#define B_OFF 16384
#define STAGE_BYTES 49152
#define STAGES 4
#define SMEM_GEMM (STAGES * STAGE_BYTES)

// ---------------- GEMM core: acc = A*B^T (fp16 in, fp32 acc) ------------------
// CTA 128(M) x 256(N), warp tile 64x64, BK=64, 256 thr, 4-stage cp.async.
// Requires: M mult of 128, K mult of 64 (except l2l pads), rows 16B aligned.
__device__ __forceinline__ void gemm_core(
    const __half* __restrict__ A_, int lda,
    const __half* __restrict__ B_, int ldb,
    int N, int K, int m0, int n0, char* smem, float (&acc)[4][8][4])
{
    const uint32_t sb = smem_to_u32(smem);
    const int tid  = threadIdx.x;
    const int lane = tid & 31;
    const int wid  = tid >> 5;
    const int wm0  = (wid >> 2) * 64;
    const int wn0  = (wid & 3) * 64;
    const int nk   = K >> 6;

#pragma unroll
    for (int i = 0; i < 4; i++)
#pragma unroll
        for (int j = 0; j < 8; j++)
#pragma unroll
            for (int q = 0; q < 4; q++) acc[i][j][q] = 0.0f;

    const int aRow = lane & 15, aSel = lane >> 4;
    const int bRow = (lane & 7) + ((lane >> 4) << 3);
    const int bSel = (lane >> 3) & 1;
    const int crow = tid >> 3;          // 0..31
    const int cch  = tid & 7;           // 16B chunk in 128B row

    auto issue = [&](int c) {
        if (c >= nk) return;
        const int kb = c * 64;
        uint32_t stb = sb + (c & (STAGES - 1)) * STAGE_BYTES;
#pragma unroll
        for (int q = 0; q < 4; q++) {
            int row = crow + q * 32;
            uint32_t so = (uint32_t)(row * 128 + (((cch ^ (row & 7)) & 7) << 4));
            size_t ga = (size_t)(m0 + row) * lda + kb + cch * 8;
            cp16(stb + A_OFF + so, A_ + ga, 16);
        }
#pragma unroll
        for (int q = 0; q < 8; q++) {
            int row = crow + q * 32;
            uint32_t so = (uint32_t)(row * 128 + (((cch ^ (row & 7)) & 7) << 4));
            int br = n0 + row;
            int ok = (br < N) ? 16 : 0;
            size_t gb = (size_t)min(br, N - 1) * ldb + kb + cch * 8;
            cp16(stb + B_OFF + so, B_ + gb, ok);
        }
    };

    issue(0); CP_COMMIT();
    issue(1); CP_COMMIT();
    issue(2); CP_COMMIT();

    for (int c = 0; c < nk; c++) {
        CP_WAIT2();               // group c complete (<=2 younger pending)
        __syncthreads();
        uint32_t stb = sb + (c & (STAGES - 1)) * STAGE_BYTES;
#pragma unroll
        for (int ks = 0; ks < 4; ks++) {
            const int kc = ks * 2;
            uint32_t aF[4][4], bF[4][4];
#pragma unroll
            for (int mf = 0; mf < 4; mf++) {
                int r = wm0 + mf * 16 + aRow;
                int ch = kc + aSel;
                uint32_t o = (uint32_t)(r * 128 + (((ch ^ (r & 7)) & 7) << 4));
                ldsm4(aF[mf], stb + A_OFF + o);
            }
#pragma unroll
            for (int gg = 0; gg < 4; gg++) {
                int r = wn0 + gg * 16 + bRow;
                int ch = kc + bSel;
                uint32_t o = (uint32_t)(r * 128 + (((ch ^ (r & 7)) & 7) << 4));
                ldsm4(bF[gg], stb + B_OFF + o);
            }
#pragma unroll
            for (int mf = 0; mf < 4; mf++) {
#pragma unroll
                for (int gg = 0; gg < 4; gg++) {
                    mma16816(acc[mf][gg * 2 + 0], aF[mf], &bF[gg][0]);
                    mma16816(acc[mf][gg * 2 + 1], aF[mf], &bF[gg][2]);
                }
            }
        }
        // buffer (c+3)&3 == (c-1)&3: its reads finished before this iter's sync
        issue(c + 3); CP_COMMIT();
    }
}

// ---------------- fused big kernel: mention scores + C1 -----------------------
// grid (8, 256): x<4 -> B=W_men_m, tanh*wo row-reduce; x>=4 -> B=W_ctx_c, store C1
__global__ __launch_bounds__(256, 1)
void gemm_big(const __half* __restrict__ eF,
              const __half* __restrict__ wmF, const __half* __restrict__ wcF,
              const float* __restrict__ wo, float* __restrict__ rowAcc,
              float* __restrict__ C1)
{
    extern __shared__ char smem[];
    const bool isMen = blockIdx.x < 4;
    const int n0 = (blockIdx.x & 3) * 256;
    const int m0 = blockIdx.y * 128;
    const int lane = threadIdx.x & 31;
    const int wid  = threadIdx.x >> 5;
    const int wm0  = (wid >> 2) * 64;
    const int wn0  = (wid & 3) * 64;

    float acc[4][8][4];
    gemm_core(eF, DIM, isMen ? wmF : wcF, DIM, DIM, DIM, m0, n0, smem, acc);

    const int g = lane >> 2, t = lane & 3;
    if (isMen) {
#pragma unroll
        for (int mf = 0; mf < 4; mf++) {
            float s0 = 0.0f, s1 = 0.0f;
#pragma unroll
            for (int nf = 0; nf < 8; nf++) {
#pragma unroll
                for (int q = 0; q < 2; q++) {
                    int n = n0 + wn0 + nf * 8 + 2 * t + q;
                    float w = wo[n];
                    s0 += ftanh(acc[mf][nf][q])     * w;
                    s1 += ftanh(acc[mf][nf][2 + q]) * w;
                }
            }
            s0 += __shfl_xor_sync(0xffffffffu, s0, 1);
            s0 += __shfl_xor_sync(0xffffffffu, s0, 2);
            s1 += __shfl_xor_sync(0xffffffffu, s1, 1);
            s1 += __shfl_xor_sync(0xffffffffu, s1, 2);
            if (t == 0) {
                int m = m0 + wm0 + mf * 16 + g;
                atomicAdd(&rowAcc[m], s0);
                atomicAdd(&rowAcc[m + 8], s1);
            }
        }
    } else {
#pragma unroll
        for (int mf = 0; mf < 4; mf++) {
            int mA = m0 + wm0 + mf * 16 + g;
#pragma unroll
            for (int nf = 0; nf < 8; nf++) {
                int n = n0 + wn0 + nf * 8 + 2 * t;
                size_t iA = (size_t)mA * DIM + n;
                size_t iB = (size_t)(mA + 8) * DIM + n;
                C1[iA]     = acc[mf][nf][0];
                C1[iA + 1] = acc[mf][nf][1];
                C1[iB]     = acc[mf][nf][2];
                C1[iB + 1] = acc[mf][nf][3];
            }
        }
    }
}

// ---------------- generic GEMM kernel (STORE / OUT epilogues) -----------------
enum { MODE_STORE = 0, MODE_OUT = 2 };

template <int MODE>
__global__ __launch_bounds__(256, 1)
void gemm_hf(const __half* __restrict__ A_, int lda,
             const __half* __restrict__ B_, int ldb,
             float* __restrict__ C, int ldc, int N, int K,
             const float* __restrict__ aux, const float* __restrict__ scal)
{
    extern __shared__ char smem[];
    const int n0 = blockIdx.x * 256;
    const int m0 = blockIdx.y * 128;
    const int lane = threadIdx.x & 31;
    const int wid  = threadIdx.x >> 5;
    const int wm0  = (wid >> 2) * 64;
    const int wn0  = (wid & 3) * 64;

    float acc[4][8][4];
    gemm_core(A_, lda, B_, ldb, N, K, m0, n0, smem, acc);

    const int g = lane >> 2, t = lane & 3;
    const float ls = (MODE == MODE_OUT) ? *scal : 0.0f;
#pragma unroll
    for (int mf = 0; mf < 4; mf++) {
        int mA = m0 + wm0 + mf * 16 + g;
#pragma unroll
        for (int nf = 0; nf < 8; nf++) {
            int n = n0 + wn0 + nf * 8 + 2 * t;
#pragma unroll
            for (int q = 0; q < 2; q++) {
                int nn = n + q;
                if (nn < N) {
                    size_t iA = (size_t)mA * ldc + nn;
                    size_t iB = (size_t)(mA + 8) * ldc + nn;
                    float v0 = acc[mf][nf][q];
                    float v1 = acc[mf][nf][2 + q];
                    if (MODE == MODE_OUT) { v0 += ls * aux[iA]; v1 += ls * aux[iB]; }
                    C[iA] = v0;
                    C[iB] = v1;
                }
            }
        }
    }
}

// ---------------- masked softmax over S + weighted sum ------------------------
__global__ void attn_kernel(const float* __restrict__ elmo,
                            const int* __restrict__ gathers,
                            const float* __restrict__ scores,
                            const float* __restrict__ mask,
                            int gatherScores,
                            float* __restrict__ outBase,
                            __half* __restrict__ outF)
{
    int b = blockIdx.x;
    int tid = threadIdx.x;
    __shared__ float attn_s[SEQ];
    __shared__ float red[8];
    int g = gathers[b];

    float sc = -1e30f;
    if (tid < SEQ) {
        float raw = gatherScores ? scores[g * SEQ + tid] : scores[b * SEQ + tid];
        sc = raw + (1.0f - mask[b * SEQ + tid]) * NEGV;
    }
    float v = sc;
#pragma unroll
    for (int off = 16; off > 0; off >>= 1)
        v = fmaxf(v, __shfl_xor_sync(0xffffffffu, v, off));
    if ((tid & 31) == 0) red[tid >> 5] = v;
    __syncthreads();
    float mx = fmaxf(fmaxf(red[0], red[1]), fmaxf(red[2], red[3]));
    __syncthreads();

    float e = (tid < SEQ) ? __expf(sc - mx) : 0.0f;
    v = e;
#pragma unroll
    for (int off = 16; off > 0; off >>= 1)
        v += __shfl_xor_sync(0xffffffffu, v, off);
    if ((tid & 31) == 0) red[tid >> 5] = v;
    __syncthreads();
    float sum = red[0] + red[1] + red[2] + red[3];
    if (tid < SEQ) attn_s[tid] = e / sum;
    __syncthreads();

    const float4* xr = reinterpret_cast<const float4*>(elmo + (size_t)g * SEQ * DIM);
    float4 accv = make_float4(0.f, 0.f, 0.f, 0.f);
#pragma unroll 4
    for (int s = 0; s < SEQ; s++) {
        float a = attn_s[s];
        float4 x = xr[(size_t)s * (DIM / 4) + tid];
        accv.x = fmaf(a, x.x, accv.x);
        accv.y = fmaf(a, x.y, accv.y);
        accv.z = fmaf(a, x.z, accv.z);
        accv.w = fmaf(a, x.w, accv.w);
    }
    size_t idx = (size_t)b * DIM2 + 4 * tid;
    *reinterpret_cast<float4*>(outBase + idx) = accv;
    __half2 h0 = __floats2half2_rn(accv.x, accv.y);
    __half2 h1 = __floats2half2_rn(accv.z, accv.w);
    uint2 o;
    o.x = *reinterpret_cast<uint32_t*>(&h0);
    o.y = *reinterpret_cast<uint32_t*>(&h1);
    *reinterpret_cast<uint2*>(outF + idx) = o;
}

// ---------------- fused context score (warp-per-s) ----------------------------
__global__ void ctx_score_kernel(const int* __restrict__ gathers,
                                 const float* __restrict__ dist,
                                 const float* __restrict__ wd,
                                 const float* __restrict__ wo)
{
    int b = blockIdx.x;
    int tid = threadIdx.x;
    int w = tid >> 5, lid = tid & 31;
    __shared__ __align__(16) float s_m2[DIM];
    __shared__ __align__(16) float s_wd[DIM];
    __shared__ __align__(16) float s_wo[DIM];
    int g = gathers[b];
    for (int i = tid; i < DIM; i += 256) {
        s_m2[i] = g_m2[(size_t)b * DIM + i];
        s_wd[i] = wd[i];
        s_wo[i] = wo[i];
    }
    __syncthreads();

    const float4* c1 = reinterpret_cast<const float4*>(g_C1) + (size_t)g * SEQ * (DIM / 4);
    const float4* m2v = reinterpret_cast<const float4*>(s_m2);
    const float4* wdv = reinterpret_cast<const float4*>(s_wd);
    const float4* wov = reinterpret_cast<const float4*>(s_wo);

    for (int s = w; s < SEQ; s += 8) {
        float dv = dist[b * SEQ + s];
        float p = 0.0f;
#pragma unroll
        for (int j0 = 0; j0 < 8; j0++) {
            int j = lid + j0 * 32;
            float4 c = c1[(size_t)s * (DIM / 4) + j];
            float4 m = m2v[j], d = wdv[j], o = wov[j];
            p += o.x * ftanh(c.x + m.x + dv * d.x)
               + o.y * ftanh(c.y + m.y + dv * d.y)
               + o.z * ftanh(c.z + m.z + dv * d.z)
               + o.w * ftanh(c.w + m.w + dv * d.w);
        }
#pragma unroll
        for (int off = 16; off > 0; off >>= 1)
            p += __shfl_xor_sync(0xffffffffu, p, off);
        if (lid == 0) g_ctxScore[b * SEQ + s] = p;
    }
}

// ---------------- latent = final @ W_f2l^T -> fp16 padded ---------------------
__global__ void latent_kernel(const float* __restrict__ Wf2l)
{
    int b = blockIdx.x;
    int tid = threadIdx.x;   // 128 threads
    __shared__ __align__(16) float4 sf[DIM2 / 4];
    const float4* fr = reinterpret_cast<const float4*>(&g_final[(size_t)b * DIM2]);
    for (int i = tid; i < DIM2 / 4; i += 128) sf[i] = fr[i];
    __syncthreads();
    float acc = 0.0f;
    if (tid < LATD) {
        const float4* wr = reinterpret_cast<const float4*>(Wf2l + (size_t)tid * DIM2);
#pragma unroll 4
        for (int k = 0; k < DIM2 / 4; k++) {
            float4 wv = wr[k];
            float4 f = sf[k];
            acc += wv.x * f.x + wv.y * f.y + wv.z * f.z + wv.w * f.w;
        }
    }
    g_latF[b * LATP + tid] = __float2half_rn(tid < LATD ? acc : 0.0f);
}

// ---------------- launch ------------------------------------------------------
extern "C" void kernel_launch(void* const* d_in, const int* in_sizes, int n_in,
                              void* d_out, int out_size)
{
    const float* elmo     = (const float*)d_in[0];
    const float* men_mask = (const float*)d_in[1];
    const float* ctx_mask = (const float*)d_in[2];
    const float* dist     = (const float*)d_in[3];
    const int*   gathers  = (const int*)  d_in[4];
    const float* W_men_m  = (const float*)d_in[5];
    const float* W_men_o  = (const float*)d_in[6];
    const float* W_ctx_c  = (const float*)d_in[7];
    const float* W_ctx_m  = (const float*)d_in[8];
    const float* w_ctx_d  = (const float*)d_in[9];
    const float* W_ctx_o  = (const float*)d_in[10];
    const float* W_out    = (const float*)d_in[11];
    const float* W_f2l    = (const float*)d_in[12];
    const float* W_l2l    = (const float*)d_in[13];
    const float* lscal    = (const float*)d_in[14];

    float* out_main = (float*)d_out;
    float* out_lat  = out_main + (size_t)BATCH * LBL;

    float *pC1, *pMS, *pCS, *pFin, *pM2;
    cudaGetSymbolAddress((void**)&pC1,  g_C1);
    cudaGetSymbolAddress((void**)&pMS,  g_menScore);
    cudaGetSymbolAddress((void**)&pCS,  g_ctxScore);
    cudaGetSymbolAddress((void**)&pFin, g_final);
    cudaGetSymbolAddress((void**)&pM2,  g_m2);
    __half *pEF, *pWmF, *pWcF, *pWcmF, *pWoF, *pl2lF, *pFF, *pLaF;
    cudaGetSymbolAddress((void**)&pEF,   g_eF);
    cudaGetSymbolAddress((void**)&pWmF,  g_WmF);
    cudaGetSymbolAddress((void**)&pWcF,  g_WcF);
    cudaGetSymbolAddress((void**)&pWcmF, g_WcmF);
    cudaGetSymbolAddress((void**)&pWoF,  g_WoF);
    cudaGetSymbolAddress((void**)&pl2lF, g_Wl2lF);
    cudaGetSymbolAddress((void**)&pFF,   g_fF);
    cudaGetSymbolAddress((void**)&pLaF,  g_latF);

    cudaFuncSetAttribute(gemm_big,            cudaFuncAttributeMaxDynamicSharedMemorySize, SMEM_GEMM);
    cudaFuncSetAttribute(gemm_hf<MODE_STORE>, cudaFuncAttributeMaxDynamicSharedMemorySize, SMEM_GEMM);
    cudaFuncSetAttribute(gemm_hf<MODE_OUT>,   cudaFuncAttributeMaxDynamicSharedMemorySize, SMEM_GEMM);

    // conversions + zero
    zero_kernel<<<(N_SENTC * SEQ + 255) / 256, 256>>>(pMS, N_SENTC * SEQ);
    {
        int n4 = (N_SENTC * SEQ * DIM) / 4;
        cvt_f16<<<(n4 + 255) / 256, 256>>>(elmo, pEF, n4);
        n4 = (DIM * DIM) / 4;
        cvt_f16<<<(n4 + 255) / 256, 256>>>(W_men_m, pWmF, n4);
        cvt_f16<<<(n4 + 255) / 256, 256>>>(W_ctx_c, pWcF, n4);
        int n4o = (int)(((size_t)LBL * DIM2) / 4);
        cvt_f16<<<(n4o + 255) / 256, 256>>>(W_out, pWoF, n4o);
    }

    // fused big GEMM: mention scores (x<4) + C1 (x>=4)
    gemm_big<<<dim3(8, 256), 256, SMEM_GEMM>>>(pEF, pWmF, pWcF, W_men_o, pMS, pC1);

    // remaining conversions (consumed later)
    {
        int n4 = (DIM * DIM) / 4;
        cvt_f16<<<(n4 + 255) / 256, 256>>>(W_ctx_m, pWcmF, n4);
        cvt_l2l<<<(LBL * LATP + 255) / 256, 256>>>(W_l2l, pl2lF);
    }

    // mention softmax + men_repr -> final cols [0,1024)
    attn_kernel<<<BATCH, 256>>>(elmo, gathers, pMS, men_mask, 1, pFin, pFF);

    // m2 = men_repr @ W_ctx_m^T  (A = fp16 final, first 1024 cols, lda=2048)
    gemm_hf<MODE_STORE><<<dim3(4, 4), 256, SMEM_GEMM>>>(
        pFF, DIM2, pWcmF, DIM, pM2, DIM, DIM, DIM, nullptr, nullptr);

    // fused context scores
    ctx_score_kernel<<<BATCH, 256>>>(gathers, dist, w_ctx_d, W_ctx_o);

    // context softmax + ctx_repr -> final cols [1024,2048)
    attn_kernel<<<BATCH, 256>>>(elmo, gathers, pCS, ctx_mask, 0, pFin + DIM, pFF + DIM);

    // latent = final @ W_f2l^T -> fp16 padded [512,128]
    latent_kernel<<<BATCH, 128>>>(W_f2l);

    // outputs_latent = latent @ W_l2l^T  (M=512, N=10331, K=128)
    gemm_hf<MODE_STORE><<<dim3(41, 4), 256, SMEM_GEMM>>>(
        pLaF, LATP, pl2lF, LATP, out_lat, LBL, LBL, LATP, nullptr, nullptr);

    // outputs = final @ W_out^T + latent_scalar * outputs_latent
    gemm_hf<MODE_OUT><<<dim3(41, 4), 256, SMEM_GEMM>>>(
        pFF, DIM2, pWoF, DIM2, out_main, LBL, LBL, DIM2, out_lat, lscal);
}

// round 12
// speedup vs baseline: 1.9782x; 1.0450x over previous
#include <cuda_runtime.h>
#include <cuda_fp16.h>
#include <cstdint>
#include <math.h>

#define N_SENTC 256
#define BATCH   512
#define SEQ     128
#define DIM     1024
#define LBL     10331
#define LATD    101
#define LATP    128
#define DIM2    2048
#define NEGV    (-10000.0f)

// ---------------- scratch -----------------------------------------------------
__device__ __half g_C1h[(size_t)N_SENTC * SEQ * DIM];   // fp16 C1
__device__ float g_menScore[N_SENTC * SEQ];
__device__ float g_ctxScore[BATCH * SEQ];
__device__ float g_final[BATCH * DIM2];
__device__ float g_m2[BATCH * DIM];

// fp16 operand scratch
__device__ __half g_eF[(size_t)N_SENTC * SEQ * DIM];
__device__ __half g_WmF[DIM * DIM];
__device__ __half g_WcF[DIM * DIM];
__device__ __half g_WcmF[DIM * DIM];
__device__ __half g_WoF[(size_t)LBL * DIM2];
__device__ __half g_Wl2lF[(size_t)LBL * LATP];
__device__ __half g_fF[BATCH * DIM2];
__device__ __half g_latF[BATCH * LATP];

// ---------------- helpers -----------------------------------------------------
__device__ __forceinline__ uint32_t smem_to_u32(const void* p) {
    uint32_t a;
    asm("{ .reg .u64 t; cvta.to.shared.u64 t, %1; cvt.u32.u64 %0, t; }" : "=r"(a) : "l"(p));
    return a;
}
__device__ __forceinline__ float ftanh(float x) {
    float e = __expf(2.0f * x);
    return 1.0f - __fdividef(2.0f, e + 1.0f);
}

__global__ void zero_kernel(float* p, int n) {
    int i = blockIdx.x * blockDim.x + threadIdx.x;
    if (i < n) p[i] = 0.0f;
}

// fp32 -> fp16 (n4 float4 groups)
__global__ void cvt_f16(const float* __restrict__ src, __half* __restrict__ dst, int n4) {
    int i = blockIdx.x * blockDim.x + threadIdx.x;
    if (i < n4) {
        float4 v = reinterpret_cast<const float4*>(src)[i];
        __half2 a = __floats2half2_rn(v.x, v.y);
        __half2 b = __floats2half2_rn(v.z, v.w);
        uint2 o;
        o.x = *reinterpret_cast<uint32_t*>(&a);
        o.y = *reinterpret_cast<uint32_t*>(&b);
        reinterpret_cast<uint2*>(dst)[i] = o;
    }
}

// W_l2l [LBL,101] fp32 -> [LBL,128] fp16 zero-padded
__global__ void cvt_l2l(const float* __restrict__ src, __half* __restrict__ dst) {
    int i = blockIdx.x * blockDim.x + threadIdx.x;
    if (i < LBL * LATP) {
        int r = i >> 7, c = i & 127;
        float v = (c < LATD) ? src[r * LATD + c] : 0.0f;
        dst[i] = __float2half_rn(v);
    }
}

// ---------------- warp-mma + cp.async primitives ------------------------------
__device__ __forceinline__ void ldsm4(uint32_t* r, uint32_t addr) {
    asm volatile("ldmatrix.sync.aligned.m8n8.x4.shared.b16 {%0,%1,%2,%3}, [%4];"
                 : "=r"(r[0]), "=r"(r[1]), "=r"(r[2]), "=r"(r[3]) : "r"(addr));
}
__device__ __forceinline__ void mma16816(float (&c)[4], const uint32_t* a, const uint32_t* b) {
    asm volatile("mma.sync.aligned.m16n8k16.row.col.f32.f16.f16.f32 "
                 "{%0,%1,%2,%3}, {%4,%5,%6,%7}, {%8,%9}, {%0,%1,%2,%3};"
                 : "+f"(c[0]), "+f"(c[1]), "+f"(c[2]), "+f"(c[3])
                 : "r"(a[0]), "r"(a[1]), "r"(a[2]), "r"(a[3]), "r"(b[0]), "r"(b[1]));
}
__device__ __forceinline__ void cp16(uint32_t saddr, const void* gaddr, int src_size) {
    asm volatile("cp.async.cg.shared.global [%0], [%1], 16, %2;"
                 :: "r"(saddr), "l"(gaddr), "r"(src_size) : "memory");
}
#define CP_COMMIT() asm volatile("cp.async.commit_group;" ::: "memory")
#define CP_WAIT2()  asm volatile("cp.async.wait_group 2;" ::: "memory")

// stage: A 128x64 fp16 (16KB) + B 256x64 fp16 (32KB); 128B rows, XOR-8 swizzle
#define A_OFF 0
#define B_OFF 16384
#define STAGE_BYTES 49152
#define STAGES 4
#define SMEM_GEMM (STAGES * STAGE_BYTES)

// ---------------- GEMM core: acc = A*B^T (fp16 in, fp32 acc) ------------------
// CTA 128(M) x 256(N), warp tile 64x64, BK=64, 256 thr, 4-stage cp.async,
// register double-buffered ldmatrix fragments.
__device__ __forceinline__ void gemm_core(
    const __half* __restrict__ A_, int lda,
    const __half* __restrict__ B_, int ldb,
    int N, int K, int m0, int n0, char* smem, float (&acc)[4][8][4])
{
    const uint32_t sb = smem_to_u32(smem);
    const int tid  = threadIdx.x;
    const int lane = tid & 31;
    const int wid  = tid >> 5;
    const int wm0  = (wid >> 2) * 64;
    const int wn0  = (wid & 3) * 64;
    const int nk   = K >> 6;

#pragma unroll
    for (int i = 0; i < 4; i++)
#pragma unroll
        for (int j = 0; j < 8; j++)
#pragma unroll
            for (int q = 0; q < 4; q++) acc[i][j][q] = 0.0f;

    const int aRow = lane & 15, aSel = lane >> 4;
    const int bRow = (lane & 7) + ((lane >> 4) << 3);
    const int bSel = (lane >> 3) & 1;
    const int crow = tid >> 3;          // 0..31
    const int cch  = tid & 7;           // 16B chunk in 128B row

    auto issue = [&](int c) {
        if (c >= nk) return;
        const int kb = c * 64;
        uint32_t stb = sb + (c & (STAGES - 1)) * STAGE_BYTES;
#pragma unroll
        for (int q = 0; q < 4; q++) {
            int row = crow + q * 32;
            uint32_t so = (uint32_t)(row * 128 + (((cch ^ (row & 7)) & 7) << 4));
            size_t ga = (size_t)(m0 + row) * lda + kb + cch * 8;
            cp16(stb + A_OFF + so, A_ + ga, 16);
        }
#pragma unroll
        for (int q = 0; q < 8; q++) {
            int row = crow + q * 32;
            uint32_t so = (uint32_t)(row * 128 + (((cch ^ (row & 7)) & 7) << 4));
            int br = n0 + row;
            int ok = (br < N) ? 16 : 0;
            size_t gb = (size_t)min(br, N - 1) * ldb + kb + cch * 8;
            cp16(stb + B_OFF + so, B_ + gb, ok);
        }
    };

    issue(0); CP_COMMIT();
    issue(1); CP_COMMIT();
    issue(2); CP_COMMIT();

    uint32_t aF[2][4][4], bF[2][4][4];

    for (int c = 0; c < nk; c++) {
        CP_WAIT2();               // group c complete (<=2 younger pending)
        __syncthreads();
        uint32_t stb = sb + (c & (STAGES - 1)) * STAGE_BYTES;

        auto load_frags = [&](int ks, int bi) {
            const int kc = ks * 2;
#pragma unroll
            for (int mf = 0; mf < 4; mf++) {
                int r = wm0 + mf * 16 + aRow;
                int ch = kc + aSel;
                uint32_t o = (uint32_t)(r * 128 + (((ch ^ (r & 7)) & 7) << 4));
                ldsm4(aF[bi][mf], stb + A_OFF + o);
            }
#pragma unroll
            for (int gg = 0; gg < 4; gg++) {
                int r = wn0 + gg * 16 + bRow;
                int ch = kc + bSel;
                uint32_t o = (uint32_t)(r * 128 + (((ch ^ (r & 7)) & 7) << 4));
                ldsm4(bF[gg < 2 ? bi : bi][gg], stb + B_OFF + o);
            }
        };
        // NOTE: bF indexed [bi][gg] — fix lambda to use proper double buffer
        (void)load_frags;

        // manual double-buffered frag pipeline
        {
            const int kc0 = 0;
#pragma unroll
            for (int mf = 0; mf < 4; mf++) {
                int r = wm0 + mf * 16 + aRow;
                int ch = kc0 + aSel;
                uint32_t o = (uint32_t)(r * 128 + (((ch ^ (r & 7)) & 7) << 4));
                ldsm4(aF[0][mf], stb + A_OFF + o);
            }
#pragma unroll
            for (int gg = 0; gg < 4; gg++) {
                int r = wn0 + gg * 16 + bRow;
                int ch = kc0 + bSel;
                uint32_t o = (uint32_t)(r * 128 + (((ch ^ (r & 7)) & 7) << 4));
                ldsm4(bF[0][gg], stb + B_OFF + o);
            }
        }
#pragma unroll
        for (int ks = 0; ks < 4; ks++) {
            const int cur = ks & 1, nxt = cur ^ 1;
            if (ks < 3) {
                const int kc = (ks + 1) * 2;
#pragma unroll
                for (int mf = 0; mf < 4; mf++) {
                    int r = wm0 + mf * 16 + aRow;
                    int ch = kc + aSel;
                    uint32_t o = (uint32_t)(r * 128 + (((ch ^ (r & 7)) & 7) << 4));
                    ldsm4(aF[nxt][mf], stb + A_OFF + o);
                }
#pragma unroll
                for (int gg = 0; gg < 4; gg++) {
                    int r = wn0 + gg * 16 + bRow;
                    int ch = kc + bSel;
                    uint32_t o = (uint32_t)(r * 128 + (((ch ^ (r & 7)) & 7) << 4));
                    ldsm4(bF[nxt][gg], stb + B_OFF + o);
                }
            }
#pragma unroll
            for (int mf = 0; mf < 4; mf++) {
#pragma unroll
                for (int gg = 0; gg < 4; gg++) {
                    mma16816(acc[mf][gg * 2 + 0], aF[cur][mf], &bF[cur][gg][0]);
                    mma16816(acc[mf][gg * 2 + 1], aF[cur][mf], &bF[cur][gg][2]);
                }
            }
        }
        issue(c + 3); CP_COMMIT();
    }
}

// ---------------- fused big kernel: mention scores + C1 (fp16) ----------------
__global__ __launch_bounds__(256, 1)
void gemm_big(const __half* __restrict__ eF,
              const __half* __restrict__ wmF, const __half* __restrict__ wcF,
              const float* __restrict__ wo, float* __restrict__ rowAcc,
              __half* __restrict__ C1)
{
    extern __shared__ char smem[];
    const bool isMen = blockIdx.x < 4;
    const int n0 = (blockIdx.x & 3) * 256;
    const int m0 = blockIdx.y * 128;
    const int lane = threadIdx.x & 31;
    const int wid  = threadIdx.x >> 5;
    const int wm0  = (wid >> 2) * 64;
    const int wn0  = (wid & 3) * 64;

    float acc[4][8][4];
    gemm_core(eF, DIM, isMen ? wmF : wcF, DIM, DIM, DIM, m0, n0, smem, acc);

    const int g = lane >> 2, t = lane & 3;
    if (isMen) {
#pragma unroll
        for (int mf = 0; mf < 4; mf++) {
            float s0 = 0.0f, s1 = 0.0f;
#pragma unroll
            for (int nf = 0; nf < 8; nf++) {
#pragma unroll
                for (int q = 0; q < 2; q++) {
                    int n = n0 + wn0 + nf * 8 + 2 * t + q;
                    float w = wo[n];
                    s0 += ftanh(acc[mf][nf][q])     * w;
                    s1 += ftanh(acc[mf][nf][2 + q]) * w;
                }
            }
            s0 += __shfl_xor_sync(0xffffffffu, s0, 1);
            s0 += __shfl_xor_sync(0xffffffffu, s0, 2);
            s1 += __shfl_xor_sync(0xffffffffu, s1, 1);
            s1 += __shfl_xor_sync(0xffffffffu, s1, 2);
            if (t == 0) {
                int m = m0 + wm0 + mf * 16 + g;
                atomicAdd(&rowAcc[m], s0);
                atomicAdd(&rowAcc[m + 8], s1);
            }
        }
    } else {
#pragma unroll
        for (int mf = 0; mf < 4; mf++) {
            int mA = m0 + wm0 + mf * 16 + g;
#pragma unroll
            for (int nf = 0; nf < 8; nf++) {
                int n = n0 + wn0 + nf * 8 + 2 * t;
                size_t iA = (size_t)mA * DIM + n;
                size_t iB = (size_t)(mA + 8) * DIM + n;
                *reinterpret_cast<__half2*>(C1 + iA) =
                    __floats2half2_rn(acc[mf][nf][0], acc[mf][nf][1]);
                *reinterpret_cast<__half2*>(C1 + iB) =
                    __floats2half2_rn(acc[mf][nf][2], acc[mf][nf][3]);
            }
        }
    }
}

// ---------------- generic GEMM kernel (STORE / OUT epilogues) -----------------
enum { MODE_STORE = 0, MODE_OUT = 2 };

template <int MODE>
__global__ __launch_bounds__(256, 1)
void gemm_hf(const __half* __restrict__ A_, int lda,
             const __half* __restrict__ B_, int ldb,
             float* __restrict__ C, int ldc, int N, int K,
             const float* __restrict__ aux, const float* __restrict__ scal)
{
    extern __shared__ char smem[];
    const int n0 = blockIdx.x * 256;
    const int m0 = blockIdx.y * 128;
    const int lane = threadIdx.x & 31;
    const int wid  = threadIdx.x >> 5;
    const int wm0  = (wid >> 2) * 64;
    const int wn0  = (wid & 3) * 64;

    float acc[4][8][4];
    gemm_core(A_, lda, B_, ldb, N, K, m0, n0, smem, acc);

    const int g = lane >> 2, t = lane & 3;
    const float ls = (MODE == MODE_OUT) ? *scal : 0.0f;
#pragma unroll
    for (int mf = 0; mf < 4; mf++) {
        int mA = m0 + wm0 + mf * 16 + g;
#pragma unroll
        for (int nf = 0; nf < 8; nf++) {
            int n = n0 + wn0 + nf * 8 + 2 * t;
#pragma unroll
            for (int q = 0; q < 2; q++) {
                int nn = n + q;
                if (nn < N) {
                    size_t iA = (size_t)mA * ldc + nn;
                    size_t iB = (size_t)(mA + 8) * ldc + nn;
                    float v0 = acc[mf][nf][q];
                    float v1 = acc[mf][nf][2 + q];
                    if (MODE == MODE_OUT) { v0 += ls * aux[iA]; v1 += ls * aux[iB]; }
                    C[iA] = v0;
                    C[iB] = v1;
                }
            }
        }
    }
}

// ---------------- masked softmax over S + weighted sum (fp16 x) ---------------
__global__ void attn_kernel(const __half* __restrict__ elmoF,
                            const int* __restrict__ gathers,
                            const float* __restrict__ scores,
                            const float* __restrict__ mask,
                            int gatherScores,
                            float* __restrict__ outBase,
                            __half* __restrict__ outF)
{
    int b = blockIdx.x;
    int tid = threadIdx.x;
    __shared__ float attn_s[SEQ];
    __shared__ float red[8];
    int g = gathers[b];

    float sc = -1e30f;
    if (tid < SEQ) {
        float raw = gatherScores ? scores[g * SEQ + tid] : scores[b * SEQ + tid];
        sc = raw + (1.0f - mask[b * SEQ + tid]) * NEGV;
    }
    float v = sc;
#pragma unroll
    for (int off = 16; off > 0; off >>= 1)
        v = fmaxf(v, __shfl_xor_sync(0xffffffffu, v, off));
    if ((tid & 31) == 0) red[tid >> 5] = v;
    __syncthreads();
    float mx = fmaxf(fmaxf(red[0], red[1]), fmaxf(red[2], red[3]));
    __syncthreads();

    float e = (tid < SEQ) ? __expf(sc - mx) : 0.0f;
    v = e;
#pragma unroll
    for (int off = 16; off > 0; off >>= 1)
        v += __shfl_xor_sync(0xffffffffu, v, off);
    if ((tid & 31) == 0) red[tid >> 5] = v;
    __syncthreads();
    float sum = red[0] + red[1] + red[2] + red[3];
    if (tid < SEQ) attn_s[tid] = e / sum;
    __syncthreads();

    const uint2* xr = reinterpret_cast<const uint2*>(elmoF + (size_t)g * SEQ * DIM);
    float4 accv = make_float4(0.f, 0.f, 0.f, 0.f);
#pragma unroll 4
    for (int s = 0; s < SEQ; s++) {
        float a = attn_s[s];
        uint2 xp = xr[(size_t)s * (DIM / 4) + tid];
        float2 x0 = __half22float2(*reinterpret_cast<__half2*>(&xp.x));
        float2 x1 = __half22float2(*reinterpret_cast<__half2*>(&xp.y));
        accv.x = fmaf(a, x0.x, accv.x);
        accv.y = fmaf(a, x0.y, accv.y);
        accv.z = fmaf(a, x1.x, accv.z);
        accv.w = fmaf(a, x1.y, accv.w);
    }
    size_t idx = (size_t)b * DIM2 + 4 * tid;
    *reinterpret_cast<float4*>(outBase + idx) = accv;
    __half2 h0 = __floats2half2_rn(accv.x, accv.y);
    __half2 h1 = __floats2half2_rn(accv.z, accv.w);
    uint2 o;
    o.x = *reinterpret_cast<uint32_t*>(&h0);
    o.y = *reinterpret_cast<uint32_t*>(&h1);
    *reinterpret_cast<uint2*>(outF + idx) = o;
}

// ---------------- fused context score (C1 fp16, warp-per-s) -------------------
__global__ void ctx_score_kernel(const int* __restrict__ gathers,
                                 const float* __restrict__ dist,
                                 const float* __restrict__ wd,
                                 const float* __restrict__ wo)
{
    int b = blockIdx.x;
    int tid = threadIdx.x;
    int w = tid >> 5, lid = tid & 31;
    __shared__ __align__(16) float s_m2[DIM];
    __shared__ __align__(16) float s_wd[DIM];
    __shared__ __align__(16) float s_wo[DIM];
    int g = gathers[b];
    for (int i = tid; i < DIM; i += 256) {
        s_m2[i] = g_m2[(size_t)b * DIM + i];
        s_wd[i] = wd[i];
        s_wo[i] = wo[i];
    }
    __syncthreads();

    const uint2* c1 = reinterpret_cast<const uint2*>(g_C1h + (size_t)g * SEQ * DIM);
    const float4* m2v = reinterpret_cast<const float4*>(s_m2);
    const float4* wdv = reinterpret_cast<const float4*>(s_wd);
    const float4* wov = reinterpret_cast<const float4*>(s_wo);

    for (int s = w; s < SEQ; s += 8) {
        float dv = dist[b * SEQ + s];
        float p = 0.0f;
#pragma unroll
        for (int j0 = 0; j0 < 8; j0++) {
            int j = lid + j0 * 32;
            uint2 cp = c1[(size_t)s * (DIM / 4) + j];
            float2 c0 = __half22float2(*reinterpret_cast<__half2*>(&cp.x));
            float2 c1f = __half22float2(*reinterpret_cast<__half2*>(&cp.y));
            float4 m = m2v[j], d = wdv[j], o = wov[j];
            p += o.x * ftanh(c0.x  + m.x + dv * d.x)
               + o.y * ftanh(c0.y  + m.y + dv * d.y)
               + o.z * ftanh(c1f.x + m.z + dv * d.z)
               + o.w * ftanh(c1f.y + m.w + dv * d.w);
        }
#pragma unroll
        for (int off = 16; off > 0; off >>= 1)
            p += __shfl_xor_sync(0xffffffffu, p, off);
        if (lid == 0) g_ctxScore[b * SEQ + s] = p;
    }
}

// ---------------- latent = final @ W_f2l^T -> fp16 padded ---------------------
__global__ void latent_kernel(const float* __restrict__ Wf2l)
{
    int b = blockIdx.x;
    int tid = threadIdx.x;   // 128 threads
    __shared__ __align__(16) float4 sf[DIM2 / 4];
    const float4* fr = reinterpret_cast<const float4*>(&g_final[(size_t)b * DIM2]);
    for (int i = tid; i < DIM2 / 4; i += 128) sf[i] = fr[i];
    __syncthreads();
    float acc = 0.0f;
    if (tid < LATD) {
        const float4* wr = reinterpret_cast<const float4*>(Wf2l + (size_t)tid * DIM2);
#pragma unroll 4
        for (int k = 0; k < DIM2 / 4; k++) {
            float4 wv = wr[k];
            float4 f = sf[k];
            acc += wv.x * f.x + wv.y * f.y + wv.z * f.z + wv.w * f.w;
        }
    }
    g_latF[b * LATP + tid] = __float2half_rn(tid < LATD ? acc : 0.0f);
}

// ---------------- launch ------------------------------------------------------
extern "C" void kernel_launch(void* const* d_in, const int* in_sizes, int n_in,
                              void* d_out, int out_size)
{
    const float* elmo     = (const float*)d_in[0];
    const float* men_mask = (const float*)d_in[1];
    const float* ctx_mask = (const float*)d_in[2];
    const float* dist     = (const float*)d_in[3];
    const int*   gathers  = (const int*)  d_in[4];
    const float* W_men_m  = (const float*)d_in[5];
    const float* W_men_o  = (const float*)d_in[6];
    const float* W_ctx_c  = (const float*)d_in[7];
    const float* W_ctx_m  = (const float*)d_in[8];
    const float* w_ctx_d  = (const float*)d_in[9];
    const float* W_ctx_o  = (const float*)d_in[10];
    const float* W_out    = (const float*)d_in[11];
    const float* W_f2l    = (const float*)d_in[12];
    const float* W_l2l    = (const float*)d_in[13];
    const float* lscal    = (const float*)d_in[14];

    float* out_main = (float*)d_out;
    float* out_lat  = out_main + (size_t)BATCH * LBL;

    float *pMS, *pCS, *pFin, *pM2;
    __half* pC1;
    cudaGetSymbolAddress((void**)&pC1,  g_C1h);
    cudaGetSymbolAddress((void**)&pMS,  g_menScore);
    cudaGetSymbolAddress((void**)&pCS,  g_ctxScore);
    cudaGetSymbolAddress((void**)&pFin, g_final);
    cudaGetSymbolAddress((void**)&pM2,  g_m2);
    __half *pEF, *pWmF, *pWcF, *pWcmF, *pWoF, *pl2lF, *pFF, *pLaF;
    cudaGetSymbolAddress((void**)&pEF,   g_eF);
    cudaGetSymbolAddress((void**)&pWmF,  g_WmF);
    cudaGetSymbolAddress((void**)&pWcF,  g_WcF);
    cudaGetSymbolAddress((void**)&pWcmF, g_WcmF);
    cudaGetSymbolAddress((void**)&pWoF,  g_WoF);
    cudaGetSymbolAddress((void**)&pl2lF, g_Wl2lF);
    cudaGetSymbolAddress((void**)&pFF,   g_fF);
    cudaGetSymbolAddress((void**)&pLaF,  g_latF);

    cudaFuncSetAttribute(gemm_big,            cudaFuncAttributeMaxDynamicSharedMemorySize, SMEM_GEMM);
    cudaFuncSetAttribute(gemm_hf<MODE_STORE>, cudaFuncAttributeMaxDynamicSharedMemorySize, SMEM_GEMM);
    cudaFuncSetAttribute(gemm_hf<MODE_OUT>,   cudaFuncAttributeMaxDynamicSharedMemorySize, SMEM_GEMM);

    // conversions + zero
    zero_kernel<<<(N_SENTC * SEQ + 255) / 256, 256>>>(pMS, N_SENTC * SEQ);
    {
        int n4 = (N_SENTC * SEQ * DIM) / 4;
        cvt_f16<<<(n4 + 255) / 256, 256>>>(elmo, pEF, n4);
        n4 = (DIM * DIM) / 4;
        cvt_f16<<<(n4 + 255) / 256, 256>>>(W_men_m, pWmF, n4);
        cvt_f16<<<(n4 + 255) / 256, 256>>>(W_ctx_c, pWcF, n4);
        int n4o = (int)(((size_t)LBL * DIM2) / 4);
        cvt_f16<<<(n4o + 255) / 256, 256>>>(W_out, pWoF, n4o);
    }

    // fused big GEMM: mention scores (x<4) + C1 fp16 (x>=4)
    gemm_big<<<dim3(8, 256), 256, SMEM_GEMM>>>(pEF, pWmF, pWcF, W_men_o, pMS, pC1);

    // remaining conversions (consumed later)
    {
        int n4 = (DIM * DIM) / 4;
        cvt_f16<<<(n4 + 255) / 256, 256>>>(W_ctx_m, pWcmF, n4);
        cvt_l2l<<<(LBL * LATP + 255) / 256, 256>>>(W_l2l, pl2lF);
    }

    // mention softmax + men_repr -> final cols [0,1024)
    attn_kernel<<<BATCH, 256>>>(pEF, gathers, pMS, men_mask, 1, pFin, pFF);

    // m2 = men_repr @ W_ctx_m^T
    gemm_hf<MODE_STORE><<<dim3(4, 4), 256, SMEM_GEMM>>>(
        pFF, DIM2, pWcmF, DIM, pM2, DIM, DIM, DIM, nullptr, nullptr);

    // fused context scores (C1 fp16)
    ctx_score_kernel<<<BATCH, 256>>>(gathers, dist, w_ctx_d, W_ctx_o);

    // context softmax + ctx_repr -> final cols [1024,2048)
    attn_kernel<<<BATCH, 256>>>(pEF, gathers, pCS, ctx_mask, 0, pFin + DIM, pFF + DIM);

    // latent = final @ W_f2l^T -> fp16 padded [512,128]
    latent_kernel<<<BATCH, 128>>>(W_f2l);

    // outputs_latent = latent @ W_l2l^T  (M=512, N=10331, K=128)
    gemm_hf<MODE_STORE><<<dim3(41, 4), 256, SMEM_GEMM>>>(
        pLaF, LATP, pl2lF, LATP, out_lat, LBL, LBL, LATP, nullptr, nullptr);

    // outputs = final @ W_out^T + latent_scalar * outputs_latent
    gemm_hf<MODE_OUT><<<dim3(41, 4), 256, SMEM_GEMM>>>(
        pFF, DIM2, pWoF, DIM2, out_main, LBL, LBL, DIM2, out_lat, lscal);
}

// round 13
// speedup vs baseline: 2.0929x; 1.0580x over previous
#include <cuda_runtime.h>
#include <cuda_fp16.h>
#include <cstdint>
#include <math.h>

#define N_SENTC 256
#define BATCH   512
#define SEQ     128
#define DIM     1024
#define LBL     10331
#define LATD    101
#define LATP    128
#define DIM2    2048
#define NEGV    (-10000.0f)

// ---------------- scratch -----------------------------------------------------
__device__ __half g_C1h[(size_t)N_SENTC * SEQ * DIM];   // fp16 C1
__device__ float g_menScore[N_SENTC * SEQ];
__device__ float g_m2[BATCH * DIM];

// fp16 operand scratch
__device__ __half g_eF[(size_t)N_SENTC * SEQ * DIM];
__device__ __half g_WmF[DIM * DIM];
__device__ __half g_WcF[DIM * DIM];
__device__ __half g_WcmF[DIM * DIM];
__device__ __half g_WoF[(size_t)LBL * DIM2];
__device__ __half g_Wl2lF[(size_t)LBL * LATP];
__device__ __half g_Wf2lF[(size_t)LATD * DIM2];
__device__ __half g_fF[BATCH * DIM2];
__device__ __half g_latF[BATCH * LATP];

// ---------------- helpers -----------------------------------------------------
__device__ __forceinline__ uint32_t smem_to_u32(const void* p) {
    uint32_t a;
    asm("{ .reg .u64 t; cvta.to.shared.u64 t, %1; cvt.u32.u64 %0, t; }" : "=r"(a) : "l"(p));
    return a;
}
__device__ __forceinline__ float ftanh(float x) {
    float e = __expf(2.0f * x);
    return 1.0f - __fdividef(2.0f, e + 1.0f);
}

__global__ void zero_kernel(float* p, int n) {
    int i = blockIdx.x * blockDim.x + threadIdx.x;
    if (i < n) p[i] = 0.0f;
}

// fp32 -> fp16 (n4 float4 groups)
__global__ void cvt_f16(const float* __restrict__ src, __half* __restrict__ dst, int n4) {
    int i = blockIdx.x * blockDim.x + threadIdx.x;
    if (i < n4) {
        float4 v = reinterpret_cast<const float4*>(src)[i];
        __half2 a = __floats2half2_rn(v.x, v.y);
        __half2 b = __floats2half2_rn(v.z, v.w);
        uint2 o;
        o.x = *reinterpret_cast<uint32_t*>(&a);
        o.y = *reinterpret_cast<uint32_t*>(&b);
        reinterpret_cast<uint2*>(dst)[i] = o;
    }
}

// two tensors in one launch (same n4 each)
__global__ void cvt2_f16(const float* __restrict__ s1, __half* __restrict__ d1,
                         const float* __restrict__ s2, __half* __restrict__ d2, int n4) {
    int i = blockIdx.x * blockDim.x + threadIdx.x;
    const float* s = (i < n4) ? s1 : s2;
    __half* d      = (i < n4) ? d1 : d2;
    int j = (i < n4) ? i : i - n4;
    if (j < n4 && i < 2 * n4) {
        float4 v = reinterpret_cast<const float4*>(s)[j];
        __half2 a = __floats2half2_rn(v.x, v.y);
        __half2 b = __floats2half2_rn(v.z, v.w);
        uint2 o;
        o.x = *reinterpret_cast<uint32_t*>(&a);
        o.y = *reinterpret_cast<uint32_t*>(&b);
        reinterpret_cast<uint2*>(d)[j] = o;
    }
}

// W_l2l [LBL,101] fp32 -> [LBL,128] fp16 zero-padded
__global__ void cvt_l2l(const float* __restrict__ src, __half* __restrict__ dst) {
    int i = blockIdx.x * blockDim.x + threadIdx.x;
    if (i < LBL * LATP) {
        int r = i >> 7, c = i & 127;
        float v = (c < LATD) ? src[r * LATD + c] : 0.0f;
        dst[i] = __float2half_rn(v);
    }
}

// ---------------- warp-mma + cp.async primitives ------------------------------
__device__ __forceinline__ void ldsm4(uint32_t* r, uint32_t addr) {
    asm volatile("ldmatrix.sync.aligned.m8n8.x4.shared.b16 {%0,%1,%2,%3}, [%4];"
                 : "=r"(r[0]), "=r"(r[1]), "=r"(r[2]), "=r"(r[3]) : "r"(addr));
}
__device__ __forceinline__ void mma16816(float (&c)[4], const uint32_t* a, const uint32_t* b) {
    asm volatile("mma.sync.aligned.m16n8k16.row.col.f32.f16.f16.f32 "
                 "{%0,%1,%2,%3}, {%4,%5,%6,%7}, {%8,%9}, {%0,%1,%2,%3};"
                 : "+f"(c[0]), "+f"(c[1]), "+f"(c[2]), "+f"(c[3])
                 : "r"(a[0]), "r"(a[1]), "r"(a[2]), "r"(a[3]), "r"(b[0]), "r"(b[1]));
}
__device__ __forceinline__ void cp16(uint32_t saddr, const void* gaddr, int src_size) {
    asm volatile("cp.async.cg.shared.global [%0], [%1], 16, %2;"
                 :: "r"(saddr), "l"(gaddr), "r"(src_size) : "memory");
}
#define CP_COMMIT() asm volatile("cp.async.commit_group;" ::: "memory")
#define CP_WAIT2()  asm volatile("cp.async.wait_group 2;" ::: "memory")

// stage: A 128x64 fp16 (16KB) + B 256x64 fp16 (32KB); 128B rows, XOR-8 swizzle
#define A_OFF 0
#define B_OFF 16384
#define STAGE_BYTES 49152
#define STAGES 4
#define SMEM_GEMM (STAGES * STAGE_BYTES)

// ---------------- GEMM core: acc = A*B^T (fp16 in, fp32 acc) ------------------
// CTA 128(M) x 256(N), warp tile 64x64, BK=64, 256 thr, 4-stage cp.async,
// register double-buffered ldmatrix fragments.
__device__ __forceinline__ void gemm_core(
    const __half* __restrict__ A_, int lda,
    const __half* __restrict__ B_, int ldb,
    int N, int K, int m0, int n0, char* smem, float (&acc)[4][8][4])
{
    const uint32_t sb = smem_to_u32(smem);
    const int tid  = threadIdx.x;
    const int lane = tid & 31;
    const int wid  = tid >> 5;
    const int wm0  = (wid >> 2) * 64;
    const int wn0  = (wid & 3) * 64;
    const int nk   = K >> 6;

#pragma unroll
    for (int i = 0; i < 4; i++)
#pragma unroll
        for (int j = 0; j < 8; j++)
#pragma unroll
            for (int q = 0; q < 4; q++) acc[i][j][q] = 0.0f;

    const int aRow = lane & 15, aSel = lane >> 4;
    const int bRow = (lane & 7) + ((lane >> 4) << 3);
    const int bSel = (lane >> 3) & 1;
    const int crow = tid >> 3;          // 0..31
    const int cch  = tid & 7;           // 16B chunk in 128B row
    const bool fullN = (n0 + 256 <= N);

    auto issue = [&](int c) {
        if (c >= nk) return;
        const int kb = c * 64;
        uint32_t stb = sb + (c & (STAGES - 1)) * STAGE_BYTES;
#pragma unroll
        for (int q = 0; q < 4; q++) {
            int row = crow + q * 32;
            uint32_t so = (uint32_t)(row * 128 + (((cch ^ (row & 7)) & 7) << 4));
            size_t ga = (size_t)(m0 + row) * lda + kb + cch * 8;
            cp16(stb + A_OFF + so, A_ + ga, 16);
        }
        if (fullN) {
#pragma unroll
            for (int q = 0; q < 8; q++) {
                int row = crow + q * 32;
                uint32_t so = (uint32_t)(row * 128 + (((cch ^ (row & 7)) & 7) << 4));
                size_t gb = (size_t)(n0 + row) * ldb + kb + cch * 8;
                cp16(stb + B_OFF + so, B_ + gb, 16);
            }
        } else {
#pragma unroll
            for (int q = 0; q < 8; q++) {
                int row = crow + q * 32;
                uint32_t so = (uint32_t)(row * 128 + (((cch ^ (row & 7)) & 7) << 4));
                int br = n0 + row;
                int ok = (br < N) ? 16 : 0;
                size_t gb = (size_t)min(br, N - 1) * ldb + kb + cch * 8;
                cp16(stb + B_OFF + so, B_ + gb, ok);
            }
        }
    };

    issue(0); CP_COMMIT();
    issue(1); CP_COMMIT();
    issue(2); CP_COMMIT();

    uint32_t aF[2][4][4], bF[2][4][4];

    for (int c = 0; c < nk; c++) {
        CP_WAIT2();               // group c complete (<=2 younger pending)
        __syncthreads();
        uint32_t stb = sb + (c & (STAGES - 1)) * STAGE_BYTES;

        // frag pipeline: preload ks=0
        {
#pragma unroll
            for (int mf = 0; mf < 4; mf++) {
                int r = wm0 + mf * 16 + aRow;
                int ch = aSel;
                uint32_t o = (uint32_t)(r * 128 + (((ch ^ (r & 7)) & 7) << 4));
                ldsm4(aF[0][mf], stb + A_OFF + o);
            }
#pragma unroll
            for (int gg = 0; gg < 4; gg++) {
                int r = wn0 + gg * 16 + bRow;
                int ch = bSel;
                uint32_t o = (uint32_t)(r * 128 + (((ch ^ (r & 7)) & 7) << 4));
                ldsm4(bF[0][gg], stb + B_OFF + o);
            }
        }
#pragma unroll
        for (int ks = 0; ks < 4; ks++) {
            const int cur = ks & 1, nxt = cur ^ 1;
            if (ks < 3) {
                const int kc = (ks + 1) * 2;
#pragma unroll
                for (int mf = 0; mf < 4; mf++) {
                    int r = wm0 + mf * 16 + aRow;
                    int ch = kc + aSel;
                    uint32_t o = (uint32_t)(r * 128 + (((ch ^ (r & 7)) & 7) << 4));
                    ldsm4(aF[nxt][mf], stb + A_OFF + o);
                }
#pragma unroll
                for (int gg = 0; gg < 4; gg++) {
                    int r = wn0 + gg * 16 + bRow;
                    int ch = kc + bSel;
                    uint32_t o = (uint32_t)(r * 128 + (((ch ^ (r & 7)) & 7) << 4));
                    ldsm4(bF[nxt][gg], stb + B_OFF + o);
                }
            }
#pragma unroll
            for (int mf = 0; mf < 4; mf++) {
#pragma unroll
                for (int gg = 0; gg < 4; gg++) {
                    mma16816(acc[mf][gg * 2 + 0], aF[cur][mf], &bF[cur][gg][0]);
                    mma16816(acc[mf][gg * 2 + 1], aF[cur][mf], &bF[cur][gg][2]);
                }
            }
        }
        issue(c + 3); CP_COMMIT();
    }
}

// ---------------- fused big kernel: mention scores + C1 (fp16) ----------------
__global__ __launch_bounds__(256, 1)
void gemm_big(const __half* __restrict__ eF,
              const __half* __restrict__ wmF, const __half* __restrict__ wcF,
              const float* __restrict__ wo, float* __restrict__ rowAcc,
              __half* __restrict__ C1)
{
    extern __shared__ char smem[];
    const bool isMen = blockIdx.x < 4;
    const int n0 = (blockIdx.x & 3) * 256;
    const int m0 = blockIdx.y * 128;
    const int lane = threadIdx.x & 31;
    const int wid  = threadIdx.x >> 5;
    const int wm0  = (wid >> 2) * 64;
    const int wn0  = (wid & 3) * 64;

    float acc[4][8][4];
    gemm_core(eF, DIM, isMen ? wmF : wcF, DIM, DIM, DIM, m0, n0, smem, acc);

    const int g = lane >> 2, t = lane & 3;
    if (isMen) {
#pragma unroll
        for (int mf = 0; mf < 4; mf++) {
            float s0 = 0.0f, s1 = 0.0f;
#pragma unroll
            for (int nf = 0; nf < 8; nf++) {
#pragma unroll
                for (int q = 0; q < 2; q++) {
                    int n = n0 + wn0 + nf * 8 + 2 * t + q;
                    float w = wo[n];
                    s0 += ftanh(acc[mf][nf][q])     * w;
                    s1 += ftanh(acc[mf][nf][2 + q]) * w;
                }
            }
            s0 += __shfl_xor_sync(0xffffffffu, s0, 1);
            s0 += __shfl_xor_sync(0xffffffffu, s0, 2);
            s1 += __shfl_xor_sync(0xffffffffu, s1, 1);
            s1 += __shfl_xor_sync(0xffffffffu, s1, 2);
            if (t == 0) {
                int m = m0 + wm0 + mf * 16 + g;
                atomicAdd(&rowAcc[m], s0);
                atomicAdd(&rowAcc[m + 8], s1);
            }
        }
    } else {
#pragma unroll
        for (int mf = 0; mf < 4; mf++) {
            int mA = m0 + wm0 + mf * 16 + g;
#pragma unroll
            for (int nf = 0; nf < 8; nf++) {
                int n = n0 + wn0 + nf * 8 + 2 * t;
                size_t iA = (size_t)mA * DIM + n;
                size_t iB = (size_t)(mA + 8) * DIM + n;
                *reinterpret_cast<__half2*>(C1 + iA) =
                    __floats2half2_rn(acc[mf][nf][0], acc[mf][nf][1]);
                *reinterpret_cast<__half2*>(C1 + iB) =
                    __floats2half2_rn(acc[mf][nf][2], acc[mf][nf][3]);
            }
        }
    }
}

// ---------------- generic GEMM kernel epilogues --------------------------------
enum { MODE_STORE = 0, MODE_OUT = 2, MODE_LAT = 3 };

template <int MODE>
__global__ __launch_bounds__(256, 1)
void gemm_hf(const __half* __restrict__ A_, int lda,
             const __half* __restrict__ B_, int ldb,
             float* __restrict__ C, int ldc, int N, int K,
             const float* __restrict__ aux, const float* __restrict__ scal)
{
    extern __shared__ char smem[];
    const int n0 = blockIdx.x * 256;
    const int m0 = blockIdx.y * 128;
    const int lane = threadIdx.x & 31;
    const int wid  = threadIdx.x >> 5;
    const int wm0  = (wid >> 2) * 64;
    const int wn0  = (wid & 3) * 64;

    float acc[4][8][4];
    gemm_core(A_, lda, B_, ldb, N, K, m0, n0, smem, acc);

    const int g = lane >> 2, t = lane & 3;
    const float ls = (MODE == MODE_OUT) ? *scal : 0.0f;
#pragma unroll
    for (int mf = 0; mf < 4; mf++) {
        int mA = m0 + wm0 + mf * 16 + g;
#pragma unroll
        for (int nf = 0; nf < 8; nf++) {
            int n = n0 + wn0 + nf * 8 + 2 * t;
#pragma unroll
            for (int q = 0; q < 2; q++) {
                int nn = n + q;
                if (MODE == MODE_LAT) {
                    // write fp16 latent, padded to LATP cols (zeros beyond LATD)
                    if (nn < LATP) {
                        __half* Ch = reinterpret_cast<__half*>(C);
                        float v0 = (nn < LATD) ? acc[mf][nf][q]     : 0.0f;
                        float v1 = (nn < LATD) ? acc[mf][nf][2 + q] : 0.0f;
                        Ch[(size_t)mA * ldc + nn]       = __float2half_rn(v0);
                        Ch[(size_t)(mA + 8) * ldc + nn] = __float2half_rn(v1);
                    }
                } else if (nn < N) {
                    size_t iA = (size_t)mA * ldc + nn;
                    size_t iB = (size_t)(mA + 8) * ldc + nn;
                    float v0 = acc[mf][nf][q];
                    float v1 = acc[mf][nf][2 + q];
                    if (MODE == MODE_OUT) { v0 += ls * aux[iA]; v1 += ls * aux[iB]; }
                    C[iA] = v0;
                    C[iB] = v1;
                }
            }
        }
    }
}

// ---------------- mention: masked softmax + weighted sum (fp16) ---------------
__global__ void attn_kernel(const __half* __restrict__ elmoF,
                            const int* __restrict__ gathers,
                            const float* __restrict__ scores,
                            const float* __restrict__ mask,
                            __half* __restrict__ outF)
{
    int b = blockIdx.x;
    int tid = threadIdx.x;
    __shared__ float attn_s[SEQ];
    __shared__ float red[8];
    int g = gathers[b];

    float sc = -1e30f;
    if (tid < SEQ) {
        float raw = scores[g * SEQ + tid];
        sc = raw + (1.0f - mask[b * SEQ + tid]) * NEGV;
    }
    float v = sc;
#pragma unroll
    for (int off = 16; off > 0; off >>= 1)
        v = fmaxf(v, __shfl_xor_sync(0xffffffffu, v, off));
    if ((tid & 31) == 0) red[tid >> 5] = v;
    __syncthreads();
    float mx = fmaxf(fmaxf(red[0], red[1]), fmaxf(red[2], red[3]));
    __syncthreads();

    float e = (tid < SEQ) ? __expf(sc - mx) : 0.0f;
    v = e;
#pragma unroll
    for (int off = 16; off > 0; off >>= 1)
        v += __shfl_xor_sync(0xffffffffu, v, off);
    if ((tid & 31) == 0) red[tid >> 5] = v;
    __syncthreads();
    float sum = red[0] + red[1] + red[2] + red[3];
    if (tid < SEQ) attn_s[tid] = e / sum;
    __syncthreads();

    const uint2* xr = reinterpret_cast<const uint2*>(elmoF + (size_t)g * SEQ * DIM);
    float4 accv = make_float4(0.f, 0.f, 0.f, 0.f);
#pragma unroll 4
    for (int s = 0; s < SEQ; s++) {
        float a = attn_s[s];
        uint2 xp = xr[(size_t)s * (DIM / 4) + tid];
        float2 x0 = __half22float2(*reinterpret_cast<__half2*>(&xp.x));
        float2 x1 = __half22float2(*reinterpret_cast<__half2*>(&xp.y));
        accv.x = fmaf(a, x0.x, accv.x);
        accv.y = fmaf(a, x0.y, accv.y);
        accv.z = fmaf(a, x1.x, accv.z);
        accv.w = fmaf(a, x1.y, accv.w);
    }
    size_t idx = (size_t)b * DIM2 + 4 * tid;
    __half2 h0 = __floats2half2_rn(accv.x, accv.y);
    __half2 h1 = __floats2half2_rn(accv.z, accv.w);
    uint2 o;
    o.x = *reinterpret_cast<uint32_t*>(&h0);
    o.y = *reinterpret_cast<uint32_t*>(&h1);
    *reinterpret_cast<uint2*>(outF + idx) = o;
}

// ---------------- fused context: score + softmax + weighted sum ----------------
__global__ void ctx_fused_kernel(const int* __restrict__ gathers,
                                 const float* __restrict__ dist,
                                 const float* __restrict__ wd,
                                 const float* __restrict__ wo,
                                 const float* __restrict__ mask,
                                 const __half* __restrict__ elmoF,
                                 __half* __restrict__ outF)
{
    int b = blockIdx.x;
    int tid = threadIdx.x;
    int w = tid >> 5, lid = tid & 31;
    __shared__ __align__(16) float s_m2[DIM];
    __shared__ __align__(16) float s_wd[DIM];
    __shared__ __align__(16) float s_wo[DIM];
    __shared__ float s_score[SEQ];
    __shared__ float attn_s[SEQ];
    __shared__ float red[8];
    int g = gathers[b];
    for (int i = tid; i < DIM; i += 256) {
        s_m2[i] = g_m2[(size_t)b * DIM + i];
        s_wd[i] = wd[i];
        s_wo[i] = wo[i];
    }
    __syncthreads();

    // phase 1: scores (warp per s)
    const uint2* c1 = reinterpret_cast<const uint2*>(g_C1h + (size_t)g * SEQ * DIM);
    const float4* m2v = reinterpret_cast<const float4*>(s_m2);
    const float4* wdv = reinterpret_cast<const float4*>(s_wd);
    const float4* wov = reinterpret_cast<const float4*>(s_wo);

    for (int s = w; s < SEQ; s += 8) {
        float dv = dist[b * SEQ + s];
        float p = 0.0f;
#pragma unroll
        for (int j0 = 0; j0 < 8; j0++) {
            int j = lid + j0 * 32;
            uint2 cp = c1[(size_t)s * (DIM / 4) + j];
            float2 c0 = __half22float2(*reinterpret_cast<__half2*>(&cp.x));
            float2 c1f = __half22float2(*reinterpret_cast<__half2*>(&cp.y));
            float4 m = m2v[j], d = wdv[j], o = wov[j];
            p += o.x * ftanh(c0.x  + m.x + dv * d.x)
               + o.y * ftanh(c0.y  + m.y + dv * d.y)
               + o.z * ftanh(c1f.x + m.z + dv * d.z)
               + o.w * ftanh(c1f.y + m.w + dv * d.w);
        }
#pragma unroll
        for (int off = 16; off > 0; off >>= 1)
            p += __shfl_xor_sync(0xffffffffu, p, off);
        if (lid == 0) s_score[s] = p;
    }
    __syncthreads();

    // phase 2: masked softmax
    float sc = -1e30f;
    if (tid < SEQ)
        sc = s_score[tid] + (1.0f - mask[b * SEQ + tid]) * NEGV;
    float v = sc;
#pragma unroll
    for (int off = 16; off > 0; off >>= 1)
        v = fmaxf(v, __shfl_xor_sync(0xffffffffu, v, off));
    if ((tid & 31) == 0) red[tid >> 5] = v;
    __syncthreads();
    float mx = fmaxf(fmaxf(red[0], red[1]), fmaxf(red[2], red[3]));
    __syncthreads();
    float e = (tid < SEQ) ? __expf(sc - mx) : 0.0f;
    v = e;
#pragma unroll
    for (int off = 16; off > 0; off >>= 1)
        v += __shfl_xor_sync(0xffffffffu, v, off);
    if ((tid & 31) == 0) red[tid >> 5] = v;
    __syncthreads();
    float sum = red[0] + red[1] + red[2] + red[3];
    if (tid < SEQ) attn_s[tid] = e / sum;
    __syncthreads();

    // phase 3: weighted sum over elmoF
    const uint2* xr = reinterpret_cast<const uint2*>(elmoF + (size_t)g * SEQ * DIM);
    float4 accv = make_float4(0.f, 0.f, 0.f, 0.f);
#pragma unroll 4
    for (int s = 0; s < SEQ; s++) {
        float a = attn_s[s];
        uint2 xp = xr[(size_t)s * (DIM / 4) + tid];
        float2 x0 = __half22float2(*reinterpret_cast<__half2*>(&xp.x));
        float2 x1 = __half22float2(*reinterpret_cast<__half2*>(&xp.y));
        accv.x = fmaf(a, x0.x, accv.x);
        accv.y = fmaf(a, x0.y, accv.y);
        accv.z = fmaf(a, x1.x, accv.z);
        accv.w = fmaf(a, x1.y, accv.w);
    }
    size_t idx = (size_t)b * DIM2 + DIM + 4 * tid;
    __half2 h0 = __floats2half2_rn(accv.x, accv.y);
    __half2 h1 = __floats2half2_rn(accv.z, accv.w);
    uint2 o;
    o.x = *reinterpret_cast<uint32_t*>(&h0);
    o.y = *reinterpret_cast<uint32_t*>(&h1);
    *reinterpret_cast<uint2*>(outF + idx) = o;
}

// ---------------- launch ------------------------------------------------------
extern "C" void kernel_launch(void* const* d_in, const int* in_sizes, int n_in,
                              void* d_out, int out_size)
{
    const float* elmo     = (const float*)d_in[0];
    const float* men_mask = (const float*)d_in[1];
    const float* ctx_mask = (const float*)d_in[2];
    const float* dist     = (const float*)d_in[3];
    const int*   gathers  = (const int*)  d_in[4];
    const float* W_men_m  = (const float*)d_in[5];
    const float* W_men_o  = (const float*)d_in[6];
    const float* W_ctx_c  = (const float*)d_in[7];
    const float* W_ctx_m  = (const float*)d_in[8];
    const float* w_ctx_d  = (const float*)d_in[9];
    const float* W_ctx_o  = (const float*)d_in[10];
    const float* W_out    = (const float*)d_in[11];
    const float* W_f2l    = (const float*)d_in[12];
    const float* W_l2l    = (const float*)d_in[13];
    const float* lscal    = (const float*)d_in[14];

    float* out_main = (float*)d_out;
    float* out_lat  = out_main + (size_t)BATCH * LBL;

    float *pMS, *pM2;
    __half* pC1;
    cudaGetSymbolAddress((void**)&pC1,  g_C1h);
    cudaGetSymbolAddress((void**)&pMS,  g_menScore);
    cudaGetSymbolAddress((void**)&pM2,  g_m2);
    __half *pEF, *pWmF, *pWcF, *pWcmF, *pWoF, *pl2lF, *pf2lF, *pFF, *pLaF;
    cudaGetSymbolAddress((void**)&pEF,   g_eF);
    cudaGetSymbolAddress((void**)&pWmF,  g_WmF);
    cudaGetSymbolAddress((void**)&pWcF,  g_WcF);
    cudaGetSymbolAddress((void**)&pWcmF, g_WcmF);
    cudaGetSymbolAddress((void**)&pWoF,  g_WoF);
    cudaGetSymbolAddress((void**)&pl2lF, g_Wl2lF);
    cudaGetSymbolAddress((void**)&pf2lF, g_Wf2lF);
    cudaGetSymbolAddress((void**)&pFF,   g_fF);
    cudaGetSymbolAddress((void**)&pLaF,  g_latF);

    cudaFuncSetAttribute(gemm_big,            cudaFuncAttributeMaxDynamicSharedMemorySize, SMEM_GEMM);
    cudaFuncSetAttribute(gemm_hf<MODE_STORE>, cudaFuncAttributeMaxDynamicSharedMemorySize, SMEM_GEMM);
    cudaFuncSetAttribute(gemm_hf<MODE_OUT>,   cudaFuncAttributeMaxDynamicSharedMemorySize, SMEM_GEMM);
    cudaFuncSetAttribute(gemm_hf<MODE_LAT>,   cudaFuncAttributeMaxDynamicSharedMemorySize, SMEM_GEMM);

    const int nDD4 = (DIM * DIM) / 4;

    // 0. elmo fp32->fp16
    {
        int n4 = (N_SENTC * SEQ * DIM) / 4;
        cvt_f16<<<(n4 + 255) / 256, 256>>>(elmo, pEF, n4);
    }
    // 1. W_men_m + W_ctx_c in one launch
    cvt2_f16<<<(2 * nDD4 + 255) / 256, 256>>>(W_men_m, pWmF, W_ctx_c, pWcF, nDD4);
    // 2. zero mention-score accumulator
    zero_kernel<<<(N_SENTC * SEQ + 255) / 256, 256>>>(pMS, N_SENTC * SEQ);

    // 3. fused big GEMM  (ncu window lands here: launch index 3)
    gemm_big<<<dim3(8, 256), 256, SMEM_GEMM>>>(pEF, pWmF, pWcF, W_men_o, pMS, pC1);

    // 4-7. remaining conversions
    cvt_f16<<<(nDD4 + 255) / 256, 256>>>(W_ctx_m, pWcmF, nDD4);
    {
        int n4o = (int)(((size_t)LBL * DIM2) / 4);
        cvt_f16<<<(n4o + 255) / 256, 256>>>(W_out, pWoF, n4o);
    }
    cvt_l2l<<<(LBL * LATP + 255) / 256, 256>>>(W_l2l, pl2lF);
    {
        int n4f = (LATD * DIM2) / 4;
        cvt_f16<<<(n4f + 255) / 256, 256>>>(W_f2l, pf2lF, n4f);
    }

    // 8. mention softmax + men_repr -> fF cols [0,1024)
    attn_kernel<<<BATCH, 256>>>(pEF, gathers, pMS, men_mask, pFF);

    // 9. m2 = men_repr @ W_ctx_m^T
    gemm_hf<MODE_STORE><<<dim3(4, 4), 256, SMEM_GEMM>>>(
        pFF, DIM2, pWcmF, DIM, pM2, DIM, DIM, DIM, nullptr, nullptr);

    // 10. fused context: score + softmax + ctx_repr -> fF cols [1024,2048)
    ctx_fused_kernel<<<BATCH, 256>>>(gathers, dist, w_ctx_d, W_ctx_o,
                                     ctx_mask, pEF, pFF);

    // 11. latent = final @ W_f2l^T -> fp16 padded [512,128]
    gemm_hf<MODE_LAT><<<dim3(1, 4), 256, SMEM_GEMM>>>(
        pFF, DIM2, pf2lF, DIM2, (float*)pLaF, LATP, LATD, DIM2, nullptr, nullptr);

    // 12. outputs_latent = latent @ W_l2l^T  (M=512, N=10331, K=128)
    gemm_hf<MODE_STORE><<<dim3(41, 4), 256, SMEM_GEMM>>>(
        pLaF, LATP, pl2lF, LATP, out_lat, LBL, LBL, LATP, nullptr, nullptr);

    // 13. outputs = final @ W_out^T + latent_scalar * outputs_latent
    gemm_hf<MODE_OUT><<<dim3(41, 4), 256, SMEM_GEMM>>>(
        pFF, DIM2, pWoF, DIM2, out_main, LBL, LBL, DIM2, out_lat, lscal);
}

// round 14
// speedup vs baseline: 2.1057x; 1.0061x over previous
#include <cuda_runtime.h>
#include <cuda_fp16.h>
#include <cstdint>
#include <math.h>

#define N_SENTC 256
#define BATCH   512
#define SEQ     128
#define DIM     1024
#define LBL     10331
#define LATD    101
#define LATP    128
#define DIM2    2048
#define NEGV    (-10000.0f)

// ---------------- scratch -----------------------------------------------------
__device__ __half g_C1h[(size_t)N_SENTC * SEQ * DIM];   // fp16 C1
__device__ float g_menScore[N_SENTC * SEQ];
__device__ float g_m2[BATCH * DIM];

// fp16 operand scratch
__device__ __half g_eF[(size_t)N_SENTC * SEQ * DIM];
__device__ __half g_WmF[DIM * DIM];
__device__ __half g_WcF[DIM * DIM];
__device__ __half g_WcmF[DIM * DIM];
__device__ __half g_WoF[(size_t)LBL * DIM2];
__device__ __half g_Wl2lF[(size_t)LBL * LATP];
__device__ __half g_Wf2lF[(size_t)LATD * DIM2];
__device__ __half g_fF[BATCH * DIM2];
__device__ __half g_latF[BATCH * LATP];

// ---------------- helpers -----------------------------------------------------
__device__ __forceinline__ uint32_t smem_to_u32(const void* p) {
    uint32_t a;
    asm("{ .reg .u64 t; cvta.to.shared.u64 t, %1; cvt.u32.u64 %0, t; }" : "=r"(a) : "l"(p));
    return a;
}
__device__ __forceinline__ float ftanh(float x) {
    float e = __expf(2.0f * x);
    return 1.0f - __fdividef(2.0f, e + 1.0f);
}

__global__ void zero_kernel(float* p, int n) {
    int i = blockIdx.x * blockDim.x + threadIdx.x;
    if (i < n) p[i] = 0.0f;
}

__global__ void cvt_f16(const float* __restrict__ src, __half* __restrict__ dst, int n4) {
    int i = blockIdx.x * blockDim.x + threadIdx.x;
    if (i < n4) {
        float4 v = reinterpret_cast<const float4*>(src)[i];
        __half2 a = __floats2half2_rn(v.x, v.y);
        __half2 b = __floats2half2_rn(v.z, v.w);
        uint2 o;
        o.x = *reinterpret_cast<uint32_t*>(&a);
        o.y = *reinterpret_cast<uint32_t*>(&b);
        reinterpret_cast<uint2*>(dst)[i] = o;
    }
}

__global__ void cvt2_f16(const float* __restrict__ s1, __half* __restrict__ d1,
                         const float* __restrict__ s2, __half* __restrict__ d2, int n4) {
    int i = blockIdx.x * blockDim.x + threadIdx.x;
    const float* s = (i < n4) ? s1 : s2;
    __half* d      = (i < n4) ? d1 : d2;
    int j = (i < n4) ? i : i - n4;
    if (j < n4 && i < 2 * n4) {
        float4 v = reinterpret_cast<const float4*>(s)[j];
        __half2 a = __floats2half2_rn(v.x, v.y);
        __half2 b = __floats2half2_rn(v.z, v.w);
        uint2 o;
        o.x = *reinterpret_cast<uint32_t*>(&a);
        o.y = *reinterpret_cast<uint32_t*>(&b);
        reinterpret_cast<uint2*>(d)[j] = o;
    }
}

__global__ void cvt_l2l(const float* __restrict__ src, __half* __restrict__ dst) {
    int i = blockIdx.x * blockDim.x + threadIdx.x;
    if (i < LBL * LATP) {
        int r = i >> 7, c = i & 127;
        float v = (c < LATD) ? src[r * LATD + c] : 0.0f;
        dst[i] = __float2half_rn(v);
    }
}

// ---------------- warp-mma + cp.async primitives ------------------------------
__device__ __forceinline__ void ldsm4(uint32_t* r, uint32_t addr) {
    asm volatile("ldmatrix.sync.aligned.m8n8.x4.shared.b16 {%0,%1,%2,%3}, [%4];"
                 : "=r"(r[0]), "=r"(r[1]), "=r"(r[2]), "=r"(r[3]) : "r"(addr));
}
__device__ __forceinline__ void mma16816(float (&c)[4], const uint32_t* a, const uint32_t* b) {
    asm volatile("mma.sync.aligned.m16n8k16.row.col.f32.f16.f16.f32 "
                 "{%0,%1,%2,%3}, {%4,%5,%6,%7}, {%8,%9}, {%0,%1,%2,%3};"
                 : "+f"(c[0]), "+f"(c[1]), "+f"(c[2]), "+f"(c[3])
                 : "r"(a[0]), "r"(a[1]), "r"(a[2]), "r"(a[3]), "r"(b[0]), "r"(b[1]));
}
__device__ __forceinline__ void cp16(uint32_t saddr, const void* gaddr, int src_size) {
    asm volatile("cp.async.cg.shared.global [%0], [%1], 16, %2;"
                 :: "r"(saddr), "l"(gaddr), "r"(src_size) : "memory");
}
#define CP_COMMIT() asm volatile("cp.async.commit_group;" ::: "memory")
#define CP_WAIT2()  asm volatile("cp.async.wait_group 2;" ::: "memory")

// ---------------- core A: CTA 128x256, warp 64x64 ------------------------------
#define A_OFF 0
#define B_OFF 16384
#define STAGE_BYTES 49152
#define STAGES 4
#define SMEM_GEMM (STAGES * STAGE_BYTES)

__device__ __forceinline__ void gemm_core(
    const __half* __restrict__ A_, int lda,
    const __half* __restrict__ B_, int ldb,
    int N, int K, int m0, int n0, char* smem, float (&acc)[4][8][4])
{
    const uint32_t sb = smem_to_u32(smem);
    const int tid  = threadIdx.x;
    const int lane = tid & 31;
    const int wid  = tid >> 5;
    const int wm0  = (wid >> 2) * 64;
    const int wn0  = (wid & 3) * 64;
    const int nk   = K >> 6;

#pragma unroll
    for (int i = 0; i < 4; i++)
#pragma unroll
        for (int j = 0; j < 8; j++)
#pragma unroll
            for (int q = 0; q < 4; q++) acc[i][j][q] = 0.0f;

    const int aRow = lane & 15, aSel = lane >> 4;
    const int bRow = (lane & 7) + ((lane >> 4) << 3);
    const int bSel = (lane >> 3) & 1;
    const int crow = tid >> 3;
    const int cch  = tid & 7;
    const bool fullN = (n0 + 256 <= N);

    auto issue = [&](int c) {
        if (c >= nk) return;
        const int kb = c * 64;
        uint32_t stb = sb + (c & (STAGES - 1)) * STAGE_BYTES;
#pragma unroll
        for (int q = 0; q < 4; q++) {
            int row = crow + q * 32;
            uint32_t so = (uint32_t)(row * 128 + (((cch ^ (row & 7)) & 7) << 4));
            size_t ga = (size_t)(m0 + row) * lda + kb + cch * 8;
            cp16(stb + A_OFF + so, A_ + ga, 16);
        }
        if (fullN) {
#pragma unroll
            for (int q = 0; q < 8; q++) {
                int row = crow + q * 32;
                uint32_t so = (uint32_t)(row * 128 + (((cch ^ (row & 7)) & 7) << 4));
                size_t gb = (size_t)(n0 + row) * ldb + kb + cch * 8;
                cp16(stb + B_OFF + so, B_ + gb, 16);
            }
        } else {
#pragma unroll
            for (int q = 0; q < 8; q++) {
                int row = crow + q * 32;
                uint32_t so = (uint32_t)(row * 128 + (((cch ^ (row & 7)) & 7) << 4));
                int br = n0 + row;
                int ok = (br < N) ? 16 : 0;
                size_t gb = (size_t)min(br, N - 1) * ldb + kb + cch * 8;
                cp16(stb + B_OFF + so, B_ + gb, ok);
            }
        }
    };

    issue(0); CP_COMMIT();
    issue(1); CP_COMMIT();
    issue(2); CP_COMMIT();

    uint32_t aF[2][4][4], bF[2][4][4];

    for (int c = 0; c < nk; c++) {
        CP_WAIT2();
        __syncthreads();
        // issue next group immediately: overwrites stage (c-1), whose readers
        // were fenced by the barrier above
        issue(c + 3); CP_COMMIT();
        uint32_t stb = sb + (c & (STAGES - 1)) * STAGE_BYTES;

        {
#pragma unroll
            for (int mf = 0; mf < 4; mf++) {
                int r = wm0 + mf * 16 + aRow;
                int ch = aSel;
                uint32_t o = (uint32_t)(r * 128 + (((ch ^ (r & 7)) & 7) << 4));
                ldsm4(aF[0][mf], stb + A_OFF + o);
            }
#pragma unroll
            for (int gg = 0; gg < 4; gg++) {
                int r = wn0 + gg * 16 + bRow;
                int ch = bSel;
                uint32_t o = (uint32_t)(r * 128 + (((ch ^ (r & 7)) & 7) << 4));
                ldsm4(bF[0][gg], stb + B_OFF + o);
            }
        }
#pragma unroll
        for (int ks = 0; ks < 4; ks++) {
            const int cur = ks & 1, nxt = cur ^ 1;
            if (ks < 3) {
                const int kc = (ks + 1) * 2;
#pragma unroll
                for (int mf = 0; mf < 4; mf++) {
                    int r = wm0 + mf * 16 + aRow;
                    int ch = kc + aSel;
                    uint32_t o = (uint32_t)(r * 128 + (((ch ^ (r & 7)) & 7) << 4));
                    ldsm4(aF[nxt][mf], stb + A_OFF + o);
                }
#pragma unroll
                for (int gg = 0; gg < 4; gg++) {
                    int r = wn0 + gg * 16 + bRow;
                    int ch = kc + bSel;
                    uint32_t o = (uint32_t)(r * 128 + (((ch ^ (r & 7)) & 7) << 4));
                    ldsm4(bF[nxt][gg], stb + B_OFF + o);
                }
            }
#pragma unroll
            for (int mf = 0; mf < 4; mf++) {
#pragma unroll
                for (int gg = 0; gg < 4; gg++) {
                    mma16816(acc[mf][gg * 2 + 0], aF[cur][mf], &bF[cur][gg][0]);
                    mma16816(acc[mf][gg * 2 + 1], aF[cur][mf], &bF[cur][gg][2]);
                }
            }
        }
    }
}

// ---------------- core B: CTA 128x128, warp 64x32 ------------------------------
#define A128_OFF 0
#define B128_OFF 16384
#define STAGE128_BYTES 32768
#define SMEM_GEMM128 (STAGES * STAGE128_BYTES)

__device__ __forceinline__ void gemm_core128(
    const __half* __restrict__ A_, int lda,
    const __half* __restrict__ B_, int ldb,
    int N, int K, int m0, int n0, char* smem, float (&acc)[4][4][4])
{
    const uint32_t sb = smem_to_u32(smem);
    const int tid  = threadIdx.x;
    const int lane = tid & 31;
    const int wid  = tid >> 5;
    const int wm0  = (wid >> 2) * 64;
    const int wn0  = (wid & 3) * 32;
    const int nk   = K >> 6;

#pragma unroll
    for (int i = 0; i < 4; i++)
#pragma unroll
        for (int j = 0; j < 4; j++)
#pragma unroll
            for (int q = 0; q < 4; q++) acc[i][j][q] = 0.0f;

    const int aRow = lane & 15, aSel = lane >> 4;
    const int bRow = (lane & 7) + ((lane >> 4) << 3);
    const int bSel = (lane >> 3) & 1;
    const int crow = tid >> 3;
    const int cch  = tid & 7;

    auto issue = [&](int c) {
        if (c >= nk) return;
        const int kb = c * 64;
        uint32_t stb = sb + (c & (STAGES - 1)) * STAGE128_BYTES;
#pragma unroll
        for (int q = 0; q < 4; q++) {
            int row = crow + q * 32;
            uint32_t so = (uint32_t)(row * 128 + (((cch ^ (row & 7)) & 7) << 4));
            size_t ga = (size_t)(m0 + row) * lda + kb + cch * 8;
            cp16(stb + A128_OFF + so, A_ + ga, 16);
        }
#pragma unroll
        for (int q = 0; q < 4; q++) {
            int row = crow + q * 32;
            uint32_t so = (uint32_t)(row * 128 + (((cch ^ (row & 7)) & 7) << 4));
            int br = n0 + row;
            int ok = (br < N) ? 16 : 0;
            size_t gb = (size_t)min(br, N - 1) * ldb + kb + cch * 8;
            cp16(stb + B128_OFF + so, B_ + gb, ok);
        }
    };

    issue(0); CP_COMMIT();
    issue(1); CP_COMMIT();
    issue(2); CP_COMMIT();

    uint32_t aF[2][4][4], bF[2][2][4];

    for (int c = 0; c < nk; c++) {
        CP_WAIT2();
        __syncthreads();
        issue(c + 3); CP_COMMIT();
        uint32_t stb = sb + (c & (STAGES - 1)) * STAGE128_BYTES;

        {
#pragma unroll
            for (int mf = 0; mf < 4; mf++) {
                int r = wm0 + mf * 16 + aRow;
                int ch = aSel;
                uint32_t o = (uint32_t)(r * 128 + (((ch ^ (r & 7)) & 7) << 4));
                ldsm4(aF[0][mf], stb + A128_OFF + o);
            }
#pragma unroll
            for (int p = 0; p < 2; p++) {
                int r = wn0 + p * 16 + bRow;
                int ch = bSel;
                uint32_t o = (uint32_t)(r * 128 + (((ch ^ (r & 7)) & 7) << 4));
                ldsm4(bF[0][p], stb + B128_OFF + o);
            }
        }
#pragma unroll
        for (int ks = 0; ks < 4; ks++) {
            const int cur = ks & 1, nxt = cur ^ 1;
            if (ks < 3) {
                const int kc = (ks + 1) * 2;
#pragma unroll
                for (int mf = 0; mf < 4; mf++) {
                    int r = wm0 + mf * 16 + aRow;
                    int ch = kc + aSel;
                    uint32_t o = (uint32_t)(r * 128 + (((ch ^ (r & 7)) & 7) << 4));
                    ldsm4(aF[nxt][mf], stb + A128_OFF + o);
                }
#pragma unroll
                for (int p = 0; p < 2; p++) {
                    int r = wn0 + p * 16 + bRow;
                    int ch = kc + bSel;
                    uint32_t o = (uint32_t)(r * 128 + (((ch ^ (r & 7)) & 7) << 4));
                    ldsm4(bF[nxt][p], stb + B128_OFF + o);
                }
            }
#pragma unroll
            for (int mf = 0; mf < 4; mf++) {
#pragma unroll
                for (int nf = 0; nf < 4; nf++) {
                    mma16816(acc[mf][nf], aF[cur][mf], &bF[cur][nf >> 1][(nf & 1) * 2]);
                }
            }
        }
    }
}

// ---------------- fused big kernel: mention scores + C1 (fp16) ----------------
__global__ __launch_bounds__(256, 1)
void gemm_big(const __half* __restrict__ eF,
              const __half* __restrict__ wmF, const __half* __restrict__ wcF,
              const float* __restrict__ wo, float* __restrict__ rowAcc,
              __half* __restrict__ C1)
{
    extern __shared__ char smem[];
    const bool isMen = blockIdx.x < 4;
    const int n0 = (blockIdx.x & 3) * 256;
    const int m0 = blockIdx.y * 128;
    const int lane = threadIdx.x & 31;
    const int wid  = threadIdx.x >> 5;
    const int wm0  = (wid >> 2) * 64;
    const int wn0  = (wid & 3) * 64;

    float acc[4][8][4];
    gemm_core(eF, DIM, isMen ? wmF : wcF, DIM, DIM, DIM, m0, n0, smem, acc);

    const int g = lane >> 2, t = lane & 3;
    if (isMen) {
#pragma unroll
        for (int mf = 0; mf < 4; mf++) {
            float s0 = 0.0f, s1 = 0.0f;
#pragma unroll
            for (int nf = 0; nf < 8; nf++) {
#pragma unroll
                for (int q = 0; q < 2; q++) {
                    int n = n0 + wn0 + nf * 8 + 2 * t + q;
                    float w = wo[n];
                    s0 += ftanh(acc[mf][nf][q])     * w;
                    s1 += ftanh(acc[mf][nf][2 + q]) * w;
                }
            }
            s0 += __shfl_xor_sync(0xffffffffu, s0, 1);
            s0 += __shfl_xor_sync(0xffffffffu, s0, 2);
            s1 += __shfl_xor_sync(0xffffffffu, s1, 1);
            s1 += __shfl_xor_sync(0xffffffffu, s1, 2);
            if (t == 0) {
                int m = m0 + wm0 + mf * 16 + g;
                atomicAdd(&rowAcc[m], s0);
                atomicAdd(&rowAcc[m + 8], s1);
            }
        }
    } else {
#pragma unroll
        for (int mf = 0; mf < 4; mf++) {
            int mA = m0 + wm0 + mf * 16 + g;
#pragma unroll
            for (int nf = 0; nf < 8; nf++) {
                int n = n0 + wn0 + nf * 8 + 2 * t;
                size_t iA = (size_t)mA * DIM + n;
                size_t iB = (size_t)(mA + 8) * DIM + n;
                *reinterpret_cast<__half2*>(C1 + iA) =
                    __floats2half2_rn(acc[mf][nf][0], acc[mf][nf][1]);
                *reinterpret_cast<__half2*>(C1 + iB) =
                    __floats2half2_rn(acc[mf][nf][2], acc[mf][nf][3]);
            }
        }
    }
}

// ---------------- generic GEMM kernel (STORE / LAT epilogues) ------------------
enum { MODE_STORE = 0, MODE_LAT = 3 };

template <int MODE>
__global__ __launch_bounds__(256, 1)
void gemm_hf(const __half* __restrict__ A_, int lda,
             const __half* __restrict__ B_, int ldb,
             float* __restrict__ C, int ldc, int N, int K)
{
    extern __shared__ char smem[];
    const int n0 = blockIdx.x * 256;
    const int m0 = blockIdx.y * 128;
    const int lane = threadIdx.x & 31;
    const int wid  = threadIdx.x >> 5;
    const int wm0  = (wid >> 2) * 64;
    const int wn0  = (wid & 3) * 64;

    float acc[4][8][4];
    gemm_core(A_, lda, B_, ldb, N, K, m0, n0, smem, acc);

    const int g = lane >> 2, t = lane & 3;
#pragma unroll
    for (int mf = 0; mf < 4; mf++) {
        int mA = m0 + wm0 + mf * 16 + g;
#pragma unroll
        for (int nf = 0; nf < 8; nf++) {
            int n = n0 + wn0 + nf * 8 + 2 * t;
#pragma unroll
            for (int q = 0; q < 2; q++) {
                int nn = n + q;
                if (MODE == MODE_LAT) {
                    if (nn < LATP) {
                        __half* Ch = reinterpret_cast<__half*>(C);
                        float v0 = (nn < LATD) ? acc[mf][nf][q]     : 0.0f;
                        float v1 = (nn < LATD) ? acc[mf][nf][2 + q] : 0.0f;
                        Ch[(size_t)mA * ldc + nn]       = __float2half_rn(v0);
                        Ch[(size_t)(mA + 8) * ldc + nn] = __float2half_rn(v1);
                    }
                } else if (nn < N) {
                    C[(size_t)mA * ldc + nn]       = acc[mf][nf][q];
                    C[(size_t)(mA + 8) * ldc + nn] = acc[mf][nf][2 + q];
                }
            }
        }
    }
}

// ---------------- fused output head: out_lat + out_main (tile 128x128) --------
__global__ __launch_bounds__(256, 1)
void gemm_outfused(const __half* __restrict__ latF,
                   const __half* __restrict__ l2lF,
                   const __half* __restrict__ fF,
                   const __half* __restrict__ woF,
                   float* __restrict__ outLat,
                   float* __restrict__ outMain,
                   const float* __restrict__ scal)
{
    extern __shared__ char smem[];
    const int n0 = blockIdx.x * 128;
    const int m0 = blockIdx.y * 128;
    const int lane = threadIdx.x & 31;
    const int wid  = threadIdx.x >> 5;
    const int wm0  = (wid >> 2) * 64;
    const int wn0  = (wid & 3) * 32;

    // phase 1: accL = latent @ W_l2l^T   (K = 128)
    float accL[4][4][4];
    gemm_core128(latF, LATP, l2lF, LATP, LBL, LATP, m0, n0, smem, accL);
    __syncthreads();   // all warps done reading phase-1 stages before reuse

    // phase 2: acc = final @ W_out^T     (K = 2048)
    float acc[4][4][4];
    gemm_core128(fF, DIM2, woF, DIM2, LBL, DIM2, m0, n0, smem, acc);

    const int g = lane >> 2, t = lane & 3;
    const float ls = *scal;
#pragma unroll
    for (int mf = 0; mf < 4; mf++) {
        int mA = m0 + wm0 + mf * 16 + g;
#pragma unroll
        for (int nf = 0; nf < 4; nf++) {
            int n = n0 + wn0 + nf * 8 + 2 * t;
#pragma unroll
            for (int q = 0; q < 2; q++) {
                int nn = n + q;
                if (nn < LBL) {
                    size_t iA = (size_t)mA * LBL + nn;
                    size_t iB = (size_t)(mA + 8) * LBL + nn;
                    float l0 = accL[mf][nf][q];
                    float l1 = accL[mf][nf][2 + q];
                    outLat[iA]  = l0;
                    outLat[iB]  = l1;
                    outMain[iA] = acc[mf][nf][q]     + ls * l0;
                    outMain[iB] = acc[mf][nf][2 + q] + ls * l1;
                }
            }
        }
    }
}

// ---------------- mention: masked softmax + weighted sum (fp16) ---------------
__global__ void attn_kernel(const __half* __restrict__ elmoF,
                            const int* __restrict__ gathers,
                            const float* __restrict__ scores,
                            const float* __restrict__ mask,
                            __half* __restrict__ outF)
{
    int b = blockIdx.x;
    int tid = threadIdx.x;
    __shared__ float attn_s[SEQ];
    __shared__ float red[8];
    int g = gathers[b];

    float sc = -1e30f;
    if (tid < SEQ) {
        float raw = scores[g * SEQ + tid];
        sc = raw + (1.0f - mask[b * SEQ + tid]) * NEGV;
    }
    float v = sc;
#pragma unroll
    for (int off = 16; off > 0; off >>= 1)
        v = fmaxf(v, __shfl_xor_sync(0xffffffffu, v, off));
    if ((tid & 31) == 0) red[tid >> 5] = v;
    __syncthreads();
    float mx = fmaxf(fmaxf(red[0], red[1]), fmaxf(red[2], red[3]));
    __syncthreads();

    float e = (tid < SEQ) ? __expf(sc - mx) : 0.0f;
    v = e;
#pragma unroll
    for (int off = 16; off > 0; off >>= 1)
        v += __shfl_xor_sync(0xffffffffu, v, off);
    if ((tid & 31) == 0) red[tid >> 5] = v;
    __syncthreads();
    float sum = red[0] + red[1] + red[2] + red[3];
    if (tid < SEQ) attn_s[tid] = e / sum;
    __syncthreads();

    const uint2* xr = reinterpret_cast<const uint2*>(elmoF + (size_t)g * SEQ * DIM);
    float4 accv = make_float4(0.f, 0.f, 0.f, 0.f);
#pragma unroll 4
    for (int s = 0; s < SEQ; s++) {
        float a = attn_s[s];
        uint2 xp = xr[(size_t)s * (DIM / 4) + tid];
        float2 x0 = __half22float2(*reinterpret_cast<__half2*>(&xp.x));
        float2 x1 = __half22float2(*reinterpret_cast<__half2*>(&xp.y));
        accv.x = fmaf(a, x0.x, accv.x);
        accv.y = fmaf(a, x0.y, accv.y);
        accv.z = fmaf(a, x1.x, accv.z);
        accv.w = fmaf(a, x1.y, accv.w);
    }
    size_t idx = (size_t)b * DIM2 + 4 * tid;
    __half2 h0 = __floats2half2_rn(accv.x, accv.y);
    __half2 h1 = __floats2half2_rn(accv.z, accv.w);
    uint2 o;
    o.x = *reinterpret_cast<uint32_t*>(&h0);
    o.y = *reinterpret_cast<uint32_t*>(&h1);
    *reinterpret_cast<uint2*>(outF + idx) = o;
}

// ---------------- fused context: score + softmax + weighted sum ----------------
__global__ void ctx_fused_kernel(const int* __restrict__ gathers,
                                 const float* __restrict__ dist,
                                 const float* __restrict__ wd,
                                 const float* __restrict__ wo,
                                 const float* __restrict__ mask,
                                 const __half* __restrict__ elmoF,
                                 __half* __restrict__ outF)
{
    int b = blockIdx.x;
    int tid = threadIdx.x;
    int w = tid >> 5, lid = tid & 31;
    __shared__ __align__(16) float s_m2[DIM];
    __shared__ __align__(16) float s_wd[DIM];
    __shared__ __align__(16) float s_wo[DIM];
    __shared__ float s_score[SEQ];
    __shared__ float attn_s[SEQ];
    __shared__ float red[8];
    int g = gathers[b];
    for (int i = tid; i < DIM; i += 256) {
        s_m2[i] = g_m2[(size_t)b * DIM + i];
        s_wd[i] = wd[i];
        s_wo[i] = wo[i];
    }
    __syncthreads();

    const uint2* c1 = reinterpret_cast<const uint2*>(g_C1h + (size_t)g * SEQ * DIM);
    const float4* m2v = reinterpret_cast<const float4*>(s_m2);
    const float4* wdv = reinterpret_cast<const float4*>(s_wd);
    const float4* wov = reinterpret_cast<const float4*>(s_wo);

    for (int s = w; s < SEQ; s += 8) {
        float dv = dist[b * SEQ + s];
        float p = 0.0f;
#pragma unroll
        for (int j0 = 0; j0 < 8; j0++) {
            int j = lid + j0 * 32;
            uint2 cp = c1[(size_t)s * (DIM / 4) + j];
            float2 c0 = __half22float2(*reinterpret_cast<__half2*>(&cp.x));
            float2 c1f = __half22float2(*reinterpret_cast<__half2*>(&cp.y));
            float4 m = m2v[j], d = wdv[j], o = wov[j];
            p += o.x * ftanh(c0.x  + m.x + dv * d.x)
               + o.y * ftanh(c0.y  + m.y + dv * d.y)
               + o.z * ftanh(c1f.x + m.z + dv * d.z)
               + o.w * ftanh(c1f.y + m.w + dv * d.w);
        }
#pragma unroll
        for (int off = 16; off > 0; off >>= 1)
            p += __shfl_xor_sync(0xffffffffu, p, off);
        if (lid == 0) s_score[s] = p;
    }
    __syncthreads();

    float sc = -1e30f;
    if (tid < SEQ)
        sc = s_score[tid] + (1.0f - mask[b * SEQ + tid]) * NEGV;
    float v = sc;
#pragma unroll
    for (int off = 16; off > 0; off >>= 1)
        v = fmaxf(v, __shfl_xor_sync(0xffffffffu, v, off));
    if ((tid & 31) == 0) red[tid >> 5] = v;
    __syncthreads();
    float mx = fmaxf(fmaxf(red[0], red[1]), fmaxf(red[2], red[3]));
    __syncthreads();
    float e = (tid < SEQ) ? __expf(sc - mx) : 0.0f;
    v = e;
#pragma unroll
    for (int off = 16; off > 0; off >>= 1)
        v += __shfl_xor_sync(0xffffffffu, v, off);
    if ((tid & 31) == 0) red[tid >> 5] = v;
    __syncthreads();
    float sum = red[0] + red[1] + red[2] + red[3];
    if (tid < SEQ) attn_s[tid] = e / sum;
    __syncthreads();

    const uint2* xr = reinterpret_cast<const uint2*>(elmoF + (size_t)g * SEQ * DIM);
    float4 accv = make_float4(0.f, 0.f, 0.f, 0.f);
#pragma unroll 4
    for (int s = 0; s < SEQ; s++) {
        float a = attn_s[s];
        uint2 xp = xr[(size_t)s * (DIM / 4) + tid];
        float2 x0 = __half22float2(*reinterpret_cast<__half2*>(&xp.x));
        float2 x1 = __half22float2(*reinterpret_cast<__half2*>(&xp.y));
        accv.x = fmaf(a, x0.x, accv.x);
        accv.y = fmaf(a, x0.y, accv.y);
        accv.z = fmaf(a, x1.x, accv.z);
        accv.w = fmaf(a, x1.y, accv.w);
    }
    size_t idx = (size_t)b * DIM2 + DIM + 4 * tid;
    __half2 h0 = __floats2half2_rn(accv.x, accv.y);
    __half2 h1 = __floats2half2_rn(accv.z, accv.w);
    uint2 o;
    o.x = *reinterpret_cast<uint32_t*>(&h0);
    o.y = *reinterpret_cast<uint32_t*>(&h1);
    *reinterpret_cast<uint2*>(outF + idx) = o;
}

// ---------------- launch ------------------------------------------------------
extern "C" void kernel_launch(void* const* d_in, const int* in_sizes, int n_in,
                              void* d_out, int out_size)
{
    const float* elmo     = (const float*)d_in[0];
    const float* men_mask = (const float*)d_in[1];
    const float* ctx_mask = (const float*)d_in[2];
    const float* dist     = (const float*)d_in[3];
    const int*   gathers  = (const int*)  d_in[4];
    const float* W_men_m  = (const float*)d_in[5];
    const float* W_men_o  = (const float*)d_in[6];
    const float* W_ctx_c  = (const float*)d_in[7];
    const float* W_ctx_m  = (const float*)d_in[8];
    const float* w_ctx_d  = (const float*)d_in[9];
    const float* W_ctx_o  = (const float*)d_in[10];
    const float* W_out    = (const float*)d_in[11];
    const float* W_f2l    = (const float*)d_in[12];
    const float* W_l2l    = (const float*)d_in[13];
    const float* lscal    = (const float*)d_in[14];

    float* out_main = (float*)d_out;
    float* out_lat  = out_main + (size_t)BATCH * LBL;

    float *pMS, *pM2;
    __half* pC1;
    cudaGetSymbolAddress((void**)&pC1,  g_C1h);
    cudaGetSymbolAddress((void**)&pMS,  g_menScore);
    cudaGetSymbolAddress((void**)&pM2,  g_m2);
    __half *pEF, *pWmF, *pWcF, *pWcmF, *pWoF, *pl2lF, *pf2lF, *pFF, *pLaF;
    cudaGetSymbolAddress((void**)&pEF,   g_eF);
    cudaGetSymbolAddress((void**)&pWmF,  g_WmF);
    cudaGetSymbolAddress((void**)&pWcF,  g_WcF);
    cudaGetSymbolAddress((void**)&pWcmF, g_WcmF);
    cudaGetSymbolAddress((void**)&pWoF,  g_WoF);
    cudaGetSymbolAddress((void**)&pl2lF, g_Wl2lF);
    cudaGetSymbolAddress((void**)&pf2lF, g_Wf2lF);
    cudaGetSymbolAddress((void**)&pFF,   g_fF);
    cudaGetSymbolAddress((void**)&pLaF,  g_latF);

    cudaFuncSetAttribute(gemm_big,            cudaFuncAttributeMaxDynamicSharedMemorySize, SMEM_GEMM);
    cudaFuncSetAttribute(gemm_hf<MODE_STORE>, cudaFuncAttributeMaxDynamicSharedMemorySize, SMEM_GEMM);
    cudaFuncSetAttribute(gemm_hf<MODE_LAT>,   cudaFuncAttributeMaxDynamicSharedMemorySize, SMEM_GEMM);
    cudaFuncSetAttribute(gemm_outfused,       cudaFuncAttributeMaxDynamicSharedMemorySize, SMEM_GEMM128);

    const int nDD4 = (DIM * DIM) / 4;

    // 0. elmo fp32->fp16
    {
        int n4 = (N_SENTC * SEQ * DIM) / 4;
        cvt_f16<<<(n4 + 255) / 256, 256>>>(elmo, pEF, n4);
    }
    // 1. W_men_m + W_ctx_c in one launch
    cvt2_f16<<<(2 * nDD4 + 255) / 256, 256>>>(W_men_m, pWmF, W_ctx_c, pWcF, nDD4);
    // 2. zero mention-score accumulator
    zero_kernel<<<(N_SENTC * SEQ + 255) / 256, 256>>>(pMS, N_SENTC * SEQ);

    // 3. fused big GEMM (ncu window: launch index 3)
    gemm_big<<<dim3(8, 256), 256, SMEM_GEMM>>>(pEF, pWmF, pWcF, W_men_o, pMS, pC1);

    // 4-7. remaining conversions
    cvt_f16<<<(nDD4 + 255) / 256, 256>>>(W_ctx_m, pWcmF, nDD4);
    {
        int n4o = (int)(((size_t)LBL * DIM2) / 4);
        cvt_f16<<<(n4o + 255) / 256, 256>>>(W_out, pWoF, n4o);
    }
    cvt_l2l<<<(LBL * LATP + 255) / 256, 256>>>(W_l2l, pl2lF);
    {
        int n4f = (LATD * DIM2) / 4;
        cvt_f16<<<(n4f + 255) / 256, 256>>>(W_f2l, pf2lF, n4f);
    }

    // 8. mention softmax + men_repr -> fF cols [0,1024)
    attn_kernel<<<BATCH, 256>>>(pEF, gathers, pMS, men_mask, pFF);

    // 9. m2 = men_repr @ W_ctx_m^T
    gemm_hf<MODE_STORE><<<dim3(4, 4), 256, SMEM_GEMM>>>(
        pFF, DIM2, pWcmF, DIM, pM2, DIM, DIM, DIM);

    // 10. fused context: score + softmax + ctx_repr -> fF cols [1024,2048)
    ctx_fused_kernel<<<BATCH, 256>>>(gathers, dist, w_ctx_d, W_ctx_o,
                                     ctx_mask, pEF, pFF);

    // 11. latent = final @ W_f2l^T -> fp16 padded [512,128]
    gemm_hf<MODE_LAT><<<dim3(1, 4), 256, SMEM_GEMM>>>(
        pFF, DIM2, pf2lF, DIM2, (float*)pLaF, LATP, LATD, DIM2);

    // 12. fused output head: out_lat + out_main in one pass (tile 128x128)
    gemm_outfused<<<dim3((LBL + 127) / 128, 4), 256, SMEM_GEMM128>>>(
        pLaF, pl2lF, pFF, pWoF, out_lat, out_main, lscal);
}